// round 12
// baseline (speedup 1.0000x reference)
#include <cuda_runtime.h>
#include <cuda_bf16.h>
#include <cstdint>
#include <math.h>

// ---------------------------------------------------------------------------
// Scratch
// ---------------------------------------------------------------------------
__device__ float g_Qc [4*2048*256];
__device__ float g_Kc [4*2048*256];
__device__ float g_Vc [4*2048*256];
__device__ float g_Qsn[4*2048*256];
__device__ float g_Ksn[4*2048*256];
__device__ float g_Vsn[4*2048*64];
__device__ float g_Scp[8*16*64*64];   // channel gram partials [kc][bh][64*64]

// ---------------------------------------------------------------------------
// warp MMA helpers
// ---------------------------------------------------------------------------
__device__ __forceinline__ void mma8(float* c, const uint32_t* a, const uint32_t* b) {
    asm volatile("mma.sync.aligned.m16n8k8.row.col.f32.tf32.tf32.f32 "
        "{%0,%1,%2,%3}, {%4,%5,%6,%7}, {%8,%9}, {%0,%1,%2,%3};"
        : "+f"(c[0]), "+f"(c[1]), "+f"(c[2]), "+f"(c[3])
        : "r"(a[0]), "r"(a[1]), "r"(a[2]), "r"(a[3]), "r"(b[0]), "r"(b[1]));
}
__device__ __forceinline__ void mma16(float* c, const uint32_t* a, const uint32_t* b) {
    asm volatile("mma.sync.aligned.m16n8k16.row.col.f32.bf16.bf16.f32 "
        "{%0,%1,%2,%3}, {%4,%5,%6,%7}, {%8,%9}, {%0,%1,%2,%3};"
        : "+f"(c[0]), "+f"(c[1]), "+f"(c[2]), "+f"(c[3])
        : "r"(a[0]), "r"(a[1]), "r"(a[2]), "r"(a[3]), "r"(b[0]), "r"(b[1]));
}
__device__ __forceinline__ float tf32r(float x) {
    uint32_t u; asm("cvt.rna.tf32.f32 %0, %1;" : "=r"(u) : "f"(x));
    return __uint_as_float(u);
}
// pack (e0 -> low half, e1 -> high half)
__device__ __forceinline__ uint32_t packbf(float e0, float e1) {
    uint32_t r; asm("cvt.rn.bf16x2.f32 %0, %1, %2;" : "=r"(r) : "f"(e1), "f"(e0));
    return r;
}

// ===========================================================================
// Projections.
//   sel 0,1 (channel q/k): tf32 single
//   sel 2   (channel v):   tf32 3-term split (accuracy-critical mean path)
//   sel 3,4 (spatial q/k): bf16 single m16n8k16 (spat bf16-rounds them anyway)
// ===========================================================================
#define PSTR 36
#define PJ_AH 0
#define PJ_AL (128*PSTR)
#define PJ_BH (2*128*PSTR)
#define PJ_BL (3*128*PSTR)
#define PJ_SMEM (4*128*PSTR*4)
// bf16 mode overlays the same dynamic smem: A 128x40 halves, B 256x40 halves

__global__ void __launch_bounds__(256) proj_mma_kernel(
    const float* __restrict__ s, const float* __restrict__ sh,
    const float* __restrict__ Wq_c, const float* __restrict__ Wk_c,
    const float* __restrict__ Wv_c, const float* __restrict__ Wq_s,
    const float* __restrict__ Wk_s)
{
    extern __shared__ __align__(16) float sm[];
    const int tid = threadIdx.x, wid = tid >> 5, lane = tid & 31;
    const int gid = lane >> 2, tid4 = lane & 3;
    const int wm = wid >> 2, wn = wid & 3;
    const int m0 = blockIdx.x * 128, n0 = blockIdx.y * 128;
    const int sel = blockIdx.z;
    const bool split = (sel == 2);
    const bool bfmode = (sel >= 3);

    const float* X = (sel == 0) ? s : sh;
    const float* W = (sel == 0) ? Wq_c : (sel == 1) ? Wk_c : (sel == 2) ? Wv_c
                   : (sel == 3) ? Wq_s : Wk_s;
    float* dst = (sel == 0) ? g_Qc : (sel == 1) ? g_Kc : (sel == 2) ? g_Vc
               : (sel == 3) ? g_Qsn : g_Ksn;

    float acc[4][4][4];
#pragma unroll
    for (int a = 0; a < 4; a++)
#pragma unroll
        for (int b = 0; b < 4; b++)
#pragma unroll
            for (int c = 0; c < 4; c++) acc[a][b][c] = 0.f;

    if (bfmode) {
        __nv_bfloat16* sA = (__nv_bfloat16*)sm;
        __nv_bfloat16* sB = sA + 128 * 40;
        for (int kc = 0; kc < 8; kc++) {
            const int k0 = kc * 32;
#pragma unroll
            for (int i = 0; i < 4; i++) {
                int f = tid + i * 256;
                int row = f >> 3, c4 = f & 7;
                float4 v = *(const float4*)&X[(size_t)(m0 + row) * 256 + k0 + c4 * 4];
                uint32_t* dp = (uint32_t*)&sA[row * 40 + c4 * 4];
                dp[0] = packbf(v.x, v.y);
                dp[1] = packbf(v.z, v.w);
            }
#pragma unroll
            for (int i = 0; i < 8; i++) {
                int f = tid + i * 256;
                int row = f >> 3, c4 = f & 7;
                float4 w = *(const float4*)&W[(size_t)(n0 + row) * 256 + k0 + c4 * 4];
                uint32_t* dp = (uint32_t*)&sB[row * 40 + c4 * 4];
                dp[0] = packbf(w.x, w.y);
                dp[1] = packbf(w.z, w.w);
            }
            __syncthreads();
#pragma unroll
            for (int kk2 = 0; kk2 < 2; kk2++) {
                uint32_t a[4][4], bq[4][2];
#pragma unroll
                for (int mt = 0; mt < 4; mt++) {
                    int r = wm * 64 + mt * 16;
                    const uint32_t* pa = (const uint32_t*)&sA[(r + gid) * 40 + kk2 * 16 + 2 * tid4];
                    const uint32_t* pb = (const uint32_t*)&sA[(r + gid + 8) * 40 + kk2 * 16 + 2 * tid4];
                    a[mt][0] = pa[0]; a[mt][1] = pb[0];
                    a[mt][2] = pa[4]; a[mt][3] = pb[4];
                }
#pragma unroll
                for (int nt = 0; nt < 4; nt++) {
                    int n = wn * 32 + nt * 8 + gid;
                    const uint32_t* p = (const uint32_t*)&sB[n * 40 + kk2 * 16 + 2 * tid4];
                    bq[nt][0] = p[0]; bq[nt][1] = p[4];
                }
#pragma unroll
                for (int mt = 0; mt < 4; mt++)
#pragma unroll
                    for (int nt = 0; nt < 4; nt++)
                        mma16(acc[mt][nt], a[mt], bq[nt]);
            }
            __syncthreads();
        }
    } else {
        for (int kc = 0; kc < 8; kc++) {
            const int k0 = kc * 32;
#pragma unroll
            for (int i = 0; i < 4; i++) {
                int f = tid + i * 256;
                int row = f >> 3, c4 = f & 7;
                float4 v = *(const float4*)&X[(size_t)(m0 + row) * 256 + k0 + c4 * 4];
                float4 hi;
                hi.x = tf32r(v.x); hi.y = tf32r(v.y); hi.z = tf32r(v.z); hi.w = tf32r(v.w);
                *(float4*)&sm[PJ_AH + row * PSTR + c4 * 4] = hi;
                if (split) {
                    float4 lo;
                    lo.x = v.x - hi.x; lo.y = v.y - hi.y; lo.z = v.z - hi.z; lo.w = v.w - hi.w;
                    *(float4*)&sm[PJ_AL + row * PSTR + c4 * 4] = lo;
                }
                float4 w = *(const float4*)&W[(size_t)(n0 + row) * 256 + k0 + c4 * 4];
                hi.x = tf32r(w.x); hi.y = tf32r(w.y); hi.z = tf32r(w.z); hi.w = tf32r(w.w);
                *(float4*)&sm[PJ_BH + row * PSTR + c4 * 4] = hi;
                if (split) {
                    float4 lo;
                    lo.x = w.x - hi.x; lo.y = w.y - hi.y; lo.z = w.z - hi.z; lo.w = w.w - hi.w;
                    *(float4*)&sm[PJ_BL + row * PSTR + c4 * 4] = lo;
                }
            }
            __syncthreads();
#pragma unroll
            for (int kk = 0; kk < 4; kk++) {
                uint32_t ah[4][4], bh[4][2];
#pragma unroll
                for (int mt = 0; mt < 4; mt++) {
                    int r = wm * 64 + mt * 16;
                    int i0 = (r + gid) * PSTR + kk * 8 + tid4;
                    int i1 = (r + gid + 8) * PSTR + kk * 8 + tid4;
                    ah[mt][0] = *(uint32_t*)&sm[PJ_AH + i0];
                    ah[mt][1] = *(uint32_t*)&sm[PJ_AH + i1];
                    ah[mt][2] = *(uint32_t*)&sm[PJ_AH + i0 + 4];
                    ah[mt][3] = *(uint32_t*)&sm[PJ_AH + i1 + 4];
                }
#pragma unroll
                for (int nt = 0; nt < 4; nt++) {
                    int n = wn * 32 + nt * 8;
                    int i0 = (n + gid) * PSTR + kk * 8 + tid4;
                    bh[nt][0] = *(uint32_t*)&sm[PJ_BH + i0];
                    bh[nt][1] = *(uint32_t*)&sm[PJ_BH + i0 + 4];
                }
#pragma unroll
                for (int mt = 0; mt < 4; mt++)
#pragma unroll
                    for (int nt = 0; nt < 4; nt++)
                        mma8(acc[mt][nt], ah[mt], bh[nt]);
                if (split) {
                    uint32_t al[4][4], bl[4][2];
#pragma unroll
                    for (int mt = 0; mt < 4; mt++) {
                        int r = wm * 64 + mt * 16;
                        int i0 = (r + gid) * PSTR + kk * 8 + tid4;
                        int i1 = (r + gid + 8) * PSTR + kk * 8 + tid4;
                        al[mt][0] = *(uint32_t*)&sm[PJ_AL + i0];
                        al[mt][1] = *(uint32_t*)&sm[PJ_AL + i1];
                        al[mt][2] = *(uint32_t*)&sm[PJ_AL + i0 + 4];
                        al[mt][3] = *(uint32_t*)&sm[PJ_AL + i1 + 4];
                    }
#pragma unroll
                    for (int nt = 0; nt < 4; nt++) {
                        int n = wn * 32 + nt * 8;
                        int i0 = (n + gid) * PSTR + kk * 8 + tid4;
                        bl[nt][0] = *(uint32_t*)&sm[PJ_BL + i0];
                        bl[nt][1] = *(uint32_t*)&sm[PJ_BL + i0 + 4];
                    }
#pragma unroll
                    for (int mt = 0; mt < 4; mt++)
#pragma unroll
                        for (int nt = 0; nt < 4; nt++) {
                            mma8(acc[mt][nt], ah[mt], bl[nt]);
                            mma8(acc[mt][nt], al[mt], bh[nt]);
                        }
                }
            }
            __syncthreads();
        }
    }
#pragma unroll
    for (int mt = 0; mt < 4; mt++)
#pragma unroll
        for (int nt = 0; nt < 4; nt++) {
            int m = m0 + wm * 64 + mt * 16 + gid;
            int n = n0 + wn * 32 + nt * 8 + tid4 * 2;
            dst[(size_t)m * 256 + n]           = acc[mt][nt][0];
            dst[(size_t)m * 256 + n + 1]       = acc[mt][nt][1];
            dst[(size_t)(m + 8) * 256 + n]     = acc[mt][nt][2];
            dst[(size_t)(m + 8) * 256 + n + 1] = acc[mt][nt][3];
        }
}

// ===========================================================================
// v_s projection (scalar fp32, K=64)
// ===========================================================================
__global__ __launch_bounds__(256) void vproj_kernel(const float* __restrict__ X,
                                                    const float* __restrict__ W)
{
    __shared__ __align__(16) float Xs[16][68], Ws[16][68];
    const int tid = threadIdx.x, tx = tid & 15, ty = tid >> 4, m0 = blockIdx.x * 64;
    const int lkk = tid & 15, lrow = tid >> 4;
    float acc[4][4];
#pragma unroll
    for (int u = 0; u < 4; u++)
#pragma unroll
        for (int v = 0; v < 4; v++) acc[u][v] = 0.f;
    for (int k0 = 0; k0 < 64; k0 += 16) {
#pragma unroll
        for (int i = 0; i < 4; i++) {
            int row = lrow + i * 16;
            Xs[lkk][row] = X[(m0 + row) * 64 + k0 + lkk];
            Ws[lkk][row] = W[row * 64 + k0 + lkk];
        }
        __syncthreads();
#pragma unroll
        for (int k = 0; k < 16; k++) {
            float4 a = *(const float4*)&Xs[k][ty * 4];
            float4 w = *(const float4*)&Ws[k][tx * 4];
            acc[0][0]+=a.x*w.x; acc[0][1]+=a.x*w.y; acc[0][2]+=a.x*w.z; acc[0][3]+=a.x*w.w;
            acc[1][0]+=a.y*w.x; acc[1][1]+=a.y*w.y; acc[1][2]+=a.y*w.z; acc[1][3]+=a.y*w.w;
            acc[2][0]+=a.z*w.x; acc[2][1]+=a.z*w.y; acc[2][2]+=a.z*w.z; acc[2][3]+=a.z*w.w;
            acc[3][0]+=a.w*w.x; acc[3][1]+=a.w*w.y; acc[3][2]+=a.w*w.z; acc[3][3]+=a.w*w.w;
        }
        __syncthreads();
    }
#pragma unroll
    for (int u = 0; u < 4; u++)
#pragma unroll
        for (int v = 0; v < 4; v++)
            g_Vsn[(size_t)(m0 + ty * 4 + u) * 64 + tx * 4 + v] = acc[u][v];
}

// ===========================================================================
// Channel gram partials via MMA (unchanged)
// ===========================================================================
#define GSTR 36
__global__ void __launch_bounds__(256) chanS_mma_kernel()
{
    __shared__ __align__(16) float Qt[64 * GSTR], Kt[64 * GSTR];
    const int tid = threadIdx.x, wid = tid >> 5, lane = tid & 31;
    const int gid = lane >> 2, tid4 = lane & 3;
    const int wm = wid >> 2, wn = wid & 3;
    const int cid = blockIdx.x, bh = cid >> 3, kc = cid & 7;
    const int b = bh >> 2, h = bh & 3;

    float acc[2][2][4];
#pragma unroll
    for (int a = 0; a < 2; a++)
#pragma unroll
        for (int c = 0; c < 2; c++)
#pragma unroll
            for (int d = 0; d < 4; d++) acc[a][c][d] = 0.f;

    const int lr = tid >> 3;
    const int ch0 = (tid & 7) * 8;

    for (int kt = 0; kt < 8; kt++) {
        int cm = kc * 256 + kt * 32 + lr;
        int r = cm >> 2, t = cm & 3;
        const float* qb = &g_Qc[(size_t)(b * 2048 + h * 512 + r) * 256 + t * 64 + ch0];
        const float* kb = &g_Kc[(size_t)(b * 2048 + h * 512 + r) * 256 + t * 64 + ch0];
        float4 q0 = *(const float4*)qb, q1 = *(const float4*)(qb + 4);
        float4 k0 = *(const float4*)kb, k1 = *(const float4*)(kb + 4);
        Qt[(ch0+0)*GSTR + lr] = tf32r(q0.x); Qt[(ch0+1)*GSTR + lr] = tf32r(q0.y);
        Qt[(ch0+2)*GSTR + lr] = tf32r(q0.z); Qt[(ch0+3)*GSTR + lr] = tf32r(q0.w);
        Qt[(ch0+4)*GSTR + lr] = tf32r(q1.x); Qt[(ch0+5)*GSTR + lr] = tf32r(q1.y);
        Qt[(ch0+6)*GSTR + lr] = tf32r(q1.z); Qt[(ch0+7)*GSTR + lr] = tf32r(q1.w);
        Kt[(ch0+0)*GSTR + lr] = tf32r(k0.x); Kt[(ch0+1)*GSTR + lr] = tf32r(k0.y);
        Kt[(ch0+2)*GSTR + lr] = tf32r(k0.z); Kt[(ch0+3)*GSTR + lr] = tf32r(k0.w);
        Kt[(ch0+4)*GSTR + lr] = tf32r(k1.x); Kt[(ch0+5)*GSTR + lr] = tf32r(k1.y);
        Kt[(ch0+6)*GSTR + lr] = tf32r(k1.z); Kt[(ch0+7)*GSTR + lr] = tf32r(k1.w);
        __syncthreads();
#pragma unroll
        for (int kk = 0; kk < 4; kk++) {
            uint32_t af[2][4], bf[2][2];
#pragma unroll
            for (int mt = 0; mt < 2; mt++) {
                int rI = wm * 32 + mt * 16;
                int i0 = (rI + gid) * GSTR + kk * 8 + tid4;
                int i1 = (rI + gid + 8) * GSTR + kk * 8 + tid4;
                af[mt][0] = *(uint32_t*)&Qt[i0];
                af[mt][1] = *(uint32_t*)&Qt[i1];
                af[mt][2] = *(uint32_t*)&Qt[i0 + 4];
                af[mt][3] = *(uint32_t*)&Qt[i1 + 4];
            }
#pragma unroll
            for (int nt = 0; nt < 2; nt++) {
                int n = wn * 16 + nt * 8;
                int i0 = (n + gid) * GSTR + kk * 8 + tid4;
                bf[nt][0] = *(uint32_t*)&Kt[i0];
                bf[nt][1] = *(uint32_t*)&Kt[i0 + 4];
            }
#pragma unroll
            for (int mt = 0; mt < 2; mt++)
#pragma unroll
                for (int nt = 0; nt < 2; nt++)
                    mma8(acc[mt][nt], af[mt], bf[nt]);
        }
        __syncthreads();
    }
#pragma unroll
    for (int mt = 0; mt < 2; mt++)
#pragma unroll
        for (int nt = 0; nt < 2; nt++) {
            int i = wm * 32 + mt * 16 + gid;
            int j = wn * 16 + nt * 8 + tid4 * 2;
            float* o = &g_Scp[((kc * 16 + bh) << 12)];
            o[i*64 + j]       = acc[mt][nt][0];
            o[i*64 + j + 1]   = acc[mt][nt][1];
            o[(i+8)*64 + j]   = acc[mt][nt][2];
            o[(i+8)*64 + j+1] = acc[mt][nt][3];
        }
}

// ===========================================================================
// x_ca: fused (reduce + softmax) + A@V^T (3-term split).  grid (16,16).
// ===========================================================================
#define XSTR 68
#define XA_HI 0
#define XA_LO (64*XSTR)
#define XB_HI (2*64*XSTR)
#define XB_LO (XB_HI + 128*XSTR)
#define XCA_SMEM ((XB_LO + 128*XSTR) * 4)

__global__ void __launch_bounds__(256) xca_mma_kernel(float* __restrict__ out,
                                                      const float* __restrict__ temp)
{
    extern __shared__ __align__(16) float sm[];
    const int tid = threadIdx.x, wid = tid >> 5, lane = tid & 31;
    const int gid = lane >> 2, tid4 = lane & 3;
    const int wm = wid >> 2, wn = wid & 3;
    const int bh = blockIdx.x, chunk = blockIdx.y, b = bh >> 2, h = bh & 3;
    const float scale = 0.125f * temp[h];

    // reduce the 8 gram partials into raw S (L2-resident; redundant per chunk)
#pragma unroll
    for (int i = 0; i < 16; i++) {
        int e = tid + i * 256;
        float sv = 0.f;
#pragma unroll
        for (int p = 0; p < 8; p++) sv += g_Scp[((p * 16 + bh) << 12) + e];
        sm[XA_HI + (e >> 6) * XSTR + (e & 63)] = sv;
    }
    __syncthreads();
    // softmax + hi/lo split (tid<64), V chunk load by all threads
    if (tid < 64) {
        float row[64];
        float sum = 0.f;
#pragma unroll
        for (int j = 0; j < 64; j++) {
            row[j] = __expf(sm[XA_HI + tid * XSTR + j] * scale); sum += row[j];
        }
        float inv = 1.f / sum;
#pragma unroll
        for (int j = 0; j < 64; j++) {
            float a = row[j] * inv;
            float hi = tf32r(a);
            sm[XA_HI + tid * XSTR + j] = hi;
            sm[XA_LO + tid * XSTR + j] = a - hi;
        }
    }
#pragma unroll
    for (int i = 0; i < 8; i++) {
        int f4 = tid + i * 256;
        int lrw = f4 >> 4, c = (f4 & 15) * 4;
        int np = chunk * 128 + lrw;
        int r = np >> 2, t = np & 3;
        float4 v = *(const float4*)&g_Vc[(size_t)(b * 2048 + h * 512 + r) * 256 + t * 64 + c];
        float4 hi, lo;
        hi.x = tf32r(v.x); lo.x = v.x - hi.x; hi.y = tf32r(v.y); lo.y = v.y - hi.y;
        hi.z = tf32r(v.z); lo.z = v.z - hi.z; hi.w = tf32r(v.w); lo.w = v.w - hi.w;
        *(float4*)&sm[XB_HI + lrw * XSTR + c] = hi;
        *(float4*)&sm[XB_LO + lrw * XSTR + c] = lo;
    }
    __syncthreads();

    float acc[2][4][4];
#pragma unroll
    for (int a = 0; a < 2; a++)
#pragma unroll
        for (int c = 0; c < 4; c++)
#pragma unroll
            for (int d = 0; d < 4; d++) acc[a][c][d] = 0.f;

#pragma unroll
    for (int kk = 0; kk < 8; kk++) {
        uint32_t ah[2][4], al[2][4], bh4[4][2], bl4[4][2];
#pragma unroll
        for (int mt = 0; mt < 2; mt++) {
            int rI = wm * 32 + mt * 16;
            int i0 = (rI + gid) * XSTR + kk * 8 + tid4;
            int i1 = (rI + gid + 8) * XSTR + kk * 8 + tid4;
            ah[mt][0] = *(uint32_t*)&sm[XA_HI + i0];
            ah[mt][1] = *(uint32_t*)&sm[XA_HI + i1];
            ah[mt][2] = *(uint32_t*)&sm[XA_HI + i0 + 4];
            ah[mt][3] = *(uint32_t*)&sm[XA_HI + i1 + 4];
            al[mt][0] = *(uint32_t*)&sm[XA_LO + i0];
            al[mt][1] = *(uint32_t*)&sm[XA_LO + i1];
            al[mt][2] = *(uint32_t*)&sm[XA_LO + i0 + 4];
            al[mt][3] = *(uint32_t*)&sm[XA_LO + i1 + 4];
        }
#pragma unroll
        for (int nt = 0; nt < 4; nt++) {
            int n = wn * 32 + nt * 8;
            int i0 = (n + gid) * XSTR + kk * 8 + tid4;
            bh4[nt][0] = *(uint32_t*)&sm[XB_HI + i0];
            bh4[nt][1] = *(uint32_t*)&sm[XB_HI + i0 + 4];
            bl4[nt][0] = *(uint32_t*)&sm[XB_LO + i0];
            bl4[nt][1] = *(uint32_t*)&sm[XB_LO + i0 + 4];
        }
#pragma unroll
        for (int mt = 0; mt < 2; mt++)
#pragma unroll
            for (int nt = 0; nt < 4; nt++) {
                mma8(acc[mt][nt], ah[mt], bh4[nt]);
                mma8(acc[mt][nt], ah[mt], bl4[nt]);
                mma8(acc[mt][nt], al[mt], bh4[nt]);
            }
    }

#pragma unroll
    for (int mt = 0; mt < 2; mt++)
#pragma unroll
        for (int nt = 0; nt < 4; nt++) {
            int dc = wm * 32 + mt * 16 + gid;
            int np = chunk * 128 + wn * 32 + nt * 8 + tid4 * 2;
            int f0 = h * 131072 + dc * 2048 + np;
            *(float2*)&out[(size_t)(b * 2048 + (f0 >> 8)) * 320 + (f0 & 255)] =
                make_float2(acc[mt][nt][0], acc[mt][nt][1]);
            int f1 = f0 + 8 * 2048;
            *(float2*)&out[(size_t)(b * 2048 + (f1 >> 8)) * 320 + (f1 & 255)] =
                make_float2(acc[mt][nt][2], acc[mt][nt][3]);
        }
}

// ===========================================================================
// Spatial flash attention (unchanged from R10 win)
// ===========================================================================
#define SP_Q    0
#define SP_K    18432
#define SP_V    36864
#define SP_RS   41216
#define SP_VP   49408
#define SP_RSUM 53504
#define SP_CSUM 54016
#define SP_OS   0
#define SPAT_SMEM 54080

__global__ void __launch_bounds__(256, 2) spat_mma_kernel(float* __restrict__ out,
                                                          const float* __restrict__ temp2)
{
    extern __shared__ __align__(16) char smc[];
    __nv_bfloat16* sQ = (__nv_bfloat16*)(smc + SP_Q);
    __nv_bfloat16* sK = (__nv_bfloat16*)(smc + SP_K);
    __nv_bfloat16* sV = (__nv_bfloat16*)(smc + SP_V);
    float* RSa   = (float*)(smc + SP_RS);
    float* VPa   = (float*)(smc + SP_VP);
    float* RSUMa = (float*)(smc + SP_RSUM);
    float* CSUMa = (float*)(smc + SP_CSUM);

    const int tid = threadIdx.x, wid = tid >> 5, lane = tid & 31;
    const int gid = lane >> 2, t4 = lane & 3;
    const int wq = wid >> 2, wj = wid & 3;
    const int cid = blockIdx.x, qt = cid & 15, bh = cid >> 4, b = bh >> 2, h = bh & 3;
    const float scale = 0.125f * temp2[h];

    const float4* Qg = (const float4*)(g_Qsn + (size_t)(b * 2048 + h * 512 + qt * 32) * 256);
#pragma unroll
    for (int i = 0; i < 8; i++) {
        int f = tid + i * 256;
        float4 v = Qg[f];
        int q = (f >> 6) * 4 + ((f >> 4) & 3);
        int d = (f & 15) * 4;
        uint32_t* dp = (uint32_t*)&sQ[q * 72 + d];
        dp[0] = packbf(v.x * scale, v.y * scale);
        dp[1] = packbf(v.z * scale, v.w * scale);
    }

    float oc[4][2][4];
#pragma unroll
    for (int a = 0; a < 4; a++)
#pragma unroll
        for (int c = 0; c < 2; c++)
#pragma unroll
            for (int d = 0; d < 4; d++) oc[a][c][d] = 0.f;
    float lpart[8];
#pragma unroll
    for (int j = 0; j < 8; j++) lpart[j] = 0.f;
    float4 vpart = make_float4(0.f, 0.f, 0.f, 0.f);

    for (int t = 0; t < 16; t++) {
        const float4* Kg = (const float4*)(g_Ksn + (size_t)(b * 2048 + h * 512 + t * 32) * 256);
#pragma unroll
        for (int i = 0; i < 8; i++) {
            int f = tid + i * 256;
            float4 v = Kg[f];
            int q = (f >> 6) * 4 + ((f >> 4) & 3);
            int d = (f & 15) * 4;
            uint32_t* dp = (uint32_t*)&sK[q * 72 + d];
            dp[0] = packbf(v.x, v.y);
            dp[1] = packbf(v.z, v.w);
        }
        const float4* Vg = (const float4*)(g_Vsn + (size_t)(b * 2048 + h * 512 + t * 32) * 64);
#pragma unroll
        for (int u = 0; u < 2; u++) {
            int f = tid + u * 256;
            float4 v = Vg[f];
            vpart.x += v.x; vpart.y += v.y; vpart.z += v.z; vpart.w += v.w;
            int j = (f >> 4) * 4 + ((f & 15) >> 2);
            int dv = (f & 3) * 4;
            sV[(dv + 0) * 136 + j] = __float2bfloat16_rn(v.x);
            sV[(dv + 1) * 136 + j] = __float2bfloat16_rn(v.y);
            sV[(dv + 2) * 136 + j] = __float2bfloat16_rn(v.z);
            sV[(dv + 3) * 136 + j] = __float2bfloat16_rn(v.w);
        }
        __syncthreads();

#pragma unroll
        for (int mp = 0; mp < 2; mp++) {
            float accS[2][4][4];
#pragma unroll
            for (int a = 0; a < 2; a++)
#pragma unroll
                for (int c = 0; c < 4; c++)
#pragma unroll
                    for (int d = 0; d < 4; d++) accS[a][c][d] = 0.f;

#pragma unroll
            for (int kk = 0; kk < 4; kk++) {
                uint32_t bK[4][2];
#pragma unroll
                for (int nt = 0; nt < 4; nt++) {
                    int n = wj * 32 + nt * 8 + gid;
                    const uint32_t* p = (const uint32_t*)&sK[n * 72 + kk * 16 + 2 * t4];
                    bK[nt][0] = p[0];
                    bK[nt][1] = p[4];
                }
#pragma unroll
                for (int mi = 0; mi < 2; mi++) {
                    int r = wq * 64 + (mp * 2 + mi) * 16;
                    const uint32_t* pa = (const uint32_t*)&sQ[(r + gid) * 72 + kk * 16 + 2 * t4];
                    const uint32_t* pb = (const uint32_t*)&sQ[(r + gid + 8) * 72 + kk * 16 + 2 * t4];
                    uint32_t a[4] = { pa[0], pb[0], pa[4], pb[4] };
#pragma unroll
                    for (int nt = 0; nt < 4; nt++)
                        mma16(accS[mi][nt], a, bK[nt]);
                }
            }

            uint32_t pA[2][2][4];
#pragma unroll
            for (int mi = 0; mi < 2; mi++) {
#pragma unroll
                for (int nt = 0; nt < 4; nt++) {
                    float pm[4];
#pragma unroll
                    for (int c = 0; c < 4; c++) {
                        float x = accS[mi][nt][c];
                        float tt = fmaf(x, 0.16666667f, 0.5f);
                        tt = fmaf(x, tt, 1.0f);
                        pm[c] = x * tt;
                    }
                    lpart[(mp * 2 + mi) * 2]     += pm[0] + pm[1];
                    lpart[(mp * 2 + mi) * 2 + 1] += pm[2] + pm[3];
                    int kk2 = nt >> 1, half = nt & 1;
                    pA[mi][kk2][half ? 2 : 0] = packbf(pm[0], pm[1]);
                    pA[mi][kk2][half ? 3 : 1] = packbf(pm[2], pm[3]);
                }
            }
#pragma unroll
            for (int kk2 = 0; kk2 < 2; kk2++) {
                uint32_t bV[2][2];
#pragma unroll
                for (int ntv = 0; ntv < 2; ntv++) {
                    const uint32_t* p = (const uint32_t*)&sV[(ntv * 8 + gid) * 136 + wj * 32 + kk2 * 16 + 2 * t4];
                    bV[ntv][0] = p[0];
                    bV[ntv][1] = p[4];
                }
#pragma unroll
                for (int mi = 0; mi < 2; mi++)
#pragma unroll
                    for (int ntv = 0; ntv < 2; ntv++)
                        mma16(oc[mp * 2 + mi][ntv], pA[mi][kk2], bV[ntv]);
            }
        }
        __syncthreads();
    }

#pragma unroll
    for (int j = 0; j < 8; j++) {
        int row = wq * 64 + (j >> 1) * 16 + (j & 1) * 8 + gid;
        RSa[row * 16 + wj * 4 + t4] = lpart[j];
    }
    *(float4*)&VPa[tid * 4] = vpart;
    float* OS = (float*)(smc + SP_OS);
#pragma unroll
    for (int mt = 0; mt < 4; mt++)
#pragma unroll
        for (int ntv = 0; ntv < 2; ntv++) {
            int r = wq * 64 + mt * 16 + gid;
            *(float2*)&OS[wj * 2048 + r * 16 + ntv * 8 + 2 * t4] =
                make_float2(oc[mt][ntv][0], oc[mt][ntv][1]);
            *(float2*)&OS[wj * 2048 + (r + 8) * 16 + ntv * 8 + 2 * t4] =
                make_float2(oc[mt][ntv][2], oc[mt][ntv][3]);
        }
    __syncthreads();
    if (tid < 128) {
        float a = 0.f;
#pragma unroll
        for (int i = 0; i < 16; i++) a += RSa[tid * 16 + i];
        RSUMa[tid] = 2048.0f + a;
    }
    if (tid < 16) {
        int g = tid >> 2, comp = tid & 3;
        float a = 0.f;
        for (int j = 0; j < 64; j++) a += VPa[(j * 4 + g) * 4 + comp];
        CSUMa[tid] = a;
    }
    __syncthreads();

    const int row = tid >> 1, c0 = (tid & 1) * 8;
    const float inv = 1.f / RSUMa[row];
    float x[8];
#pragma unroll
    for (int i = 0; i < 8; i++) {
        float o = CSUMa[c0 + i];
#pragma unroll
        for (int w = 0; w < 4; w++) o += OS[w * 2048 + row * 16 + c0 + i];
        x[i] = o * inv;
    }
    const int n = qt * 128 + row;
    const int f0 = h * 32768 + n * 16 + c0;
    float* og = out + (size_t)(b * 2048 + (f0 >> 6)) * 320 + 256 + (f0 & 63);
    *(float4*)&og[0] = make_float4(x[0], x[1], x[2], x[3]);
    *(float4*)&og[4] = make_float4(x[4], x[5], x[6], x[7]);
}

// ===========================================================================
// Launcher
// ===========================================================================
extern "C" void kernel_launch(void* const* d_in, const int* in_sizes, int n_in,
                              void* d_out, int out_size)
{
    const float* s     = (const float*)d_in[0];
    const float* h     = (const float*)d_in[1];
    const float* sh    = (const float*)d_in[2];
    const float* temp  = (const float*)d_in[3];
    const float* temp2 = (const float*)d_in[4];
    const float* Wq_c  = (const float*)d_in[5];
    const float* Wq_s  = (const float*)d_in[6];
    const float* Wk_c  = (const float*)d_in[7];
    const float* Wv_c  = (const float*)d_in[8];
    const float* Wk_s  = (const float*)d_in[9];
    const float* Wv_s  = (const float*)d_in[10];
    float* out = (float*)d_out;

    cudaFuncSetAttribute(proj_mma_kernel, cudaFuncAttributeMaxDynamicSharedMemorySize, PJ_SMEM);
    cudaFuncSetAttribute(xca_mma_kernel,  cudaFuncAttributeMaxDynamicSharedMemorySize, XCA_SMEM);
    cudaFuncSetAttribute(spat_mma_kernel, cudaFuncAttributeMaxDynamicSharedMemorySize, SPAT_SMEM);

    proj_mma_kernel<<<dim3(64, 2, 5), 256, PJ_SMEM>>>(s, sh, Wq_c, Wk_c, Wv_c, Wq_s, Wk_s);
    vproj_kernel<<<128, 256>>>(h, Wv_s);
    chanS_mma_kernel<<<128, 256>>>();
    xca_mma_kernel<<<dim3(16, 16), 256, XCA_SMEM>>>(out, temp);
    spat_mma_kernel<<<256, 256, SPAT_SMEM>>>(out, temp2);
}

// round 13
// speedup vs baseline: 1.0089x; 1.0089x over previous
#include <cuda_runtime.h>
#include <cuda_bf16.h>
#include <cstdint>
#include <math.h>

// ---------------------------------------------------------------------------
// Scratch
// ---------------------------------------------------------------------------
__device__ float g_Qc [4*2048*256];
__device__ float g_Kc [4*2048*256];
__device__ float g_Vc [4*2048*256];
__device__ float g_Qsn[4*2048*256];
__device__ float g_Ksn[4*2048*256];
__device__ float g_Vsn[4*2048*64];
__device__ float g_Scp[8*16*64*64];   // channel gram partials [kc][bh][64*64]

// ---------------------------------------------------------------------------
// warp MMA helpers
// ---------------------------------------------------------------------------
__device__ __forceinline__ void mma8(float* c, const uint32_t* a, const uint32_t* b) {
    asm volatile("mma.sync.aligned.m16n8k8.row.col.f32.tf32.tf32.f32 "
        "{%0,%1,%2,%3}, {%4,%5,%6,%7}, {%8,%9}, {%0,%1,%2,%3};"
        : "+f"(c[0]), "+f"(c[1]), "+f"(c[2]), "+f"(c[3])
        : "r"(a[0]), "r"(a[1]), "r"(a[2]), "r"(a[3]), "r"(b[0]), "r"(b[1]));
}
__device__ __forceinline__ void mma16(float* c, const uint32_t* a, const uint32_t* b) {
    asm volatile("mma.sync.aligned.m16n8k16.row.col.f32.bf16.bf16.f32 "
        "{%0,%1,%2,%3}, {%4,%5,%6,%7}, {%8,%9}, {%0,%1,%2,%3};"
        : "+f"(c[0]), "+f"(c[1]), "+f"(c[2]), "+f"(c[3])
        : "r"(a[0]), "r"(a[1]), "r"(a[2]), "r"(a[3]), "r"(b[0]), "r"(b[1]));
}
__device__ __forceinline__ float tf32r(float x) {
    uint32_t u; asm("cvt.rna.tf32.f32 %0, %1;" : "=r"(u) : "f"(x));
    return __uint_as_float(u);
}
// pack (e0 -> low half, e1 -> high half)
__device__ __forceinline__ uint32_t packbf(float e0, float e1) {
    uint32_t r; asm("cvt.rn.bf16x2.f32 %0, %1, %2;" : "=r"(r) : "f"(e1), "f"(e0));
    return r;
}

// ===========================================================================
// Projection kernel A: tf32 (sels 0,1 single; sel 2 = Wv_c 3-term split).
// Identical loop structure to the R10 best-known configuration.
// ===========================================================================
#define PSTR 36
#define PJ_AH 0
#define PJ_AL (128*PSTR)
#define PJ_BH (2*128*PSTR)
#define PJ_BL (3*128*PSTR)
#define PJ_SMEM (4*128*PSTR*4)

__global__ void __launch_bounds__(256) proj_tf32_kernel(
    const float* __restrict__ s, const float* __restrict__ sh,
    const float* __restrict__ Wq_c, const float* __restrict__ Wk_c,
    const float* __restrict__ Wv_c)
{
    extern __shared__ __align__(16) float sm[];
    const int tid = threadIdx.x, wid = tid >> 5, lane = tid & 31;
    const int gid = lane >> 2, tid4 = lane & 3;
    const int wm = wid >> 2, wn = wid & 3;
    const int m0 = blockIdx.x * 128, n0 = blockIdx.y * 128;
    const int sel = blockIdx.z;
    const bool split = (sel == 2);

    const float* X = (sel == 0) ? s : sh;
    const float* W = (sel == 0) ? Wq_c : (sel == 1) ? Wk_c : Wv_c;
    float* dst = (sel == 0) ? g_Qc : (sel == 1) ? g_Kc : g_Vc;

    float acc[4][4][4];
#pragma unroll
    for (int a = 0; a < 4; a++)
#pragma unroll
        for (int b = 0; b < 4; b++)
#pragma unroll
            for (int c = 0; c < 4; c++) acc[a][b][c] = 0.f;

    for (int kc = 0; kc < 8; kc++) {
        const int k0 = kc * 32;
#pragma unroll
        for (int i = 0; i < 4; i++) {
            int f = tid + i * 256;
            int row = f >> 3, c4 = f & 7;
            float4 v = *(const float4*)&X[(size_t)(m0 + row) * 256 + k0 + c4 * 4];
            float4 hi;
            hi.x = tf32r(v.x); hi.y = tf32r(v.y); hi.z = tf32r(v.z); hi.w = tf32r(v.w);
            *(float4*)&sm[PJ_AH + row * PSTR + c4 * 4] = hi;
            if (split) {
                float4 lo;
                lo.x = v.x - hi.x; lo.y = v.y - hi.y; lo.z = v.z - hi.z; lo.w = v.w - hi.w;
                *(float4*)&sm[PJ_AL + row * PSTR + c4 * 4] = lo;
            }
            float4 w = *(const float4*)&W[(size_t)(n0 + row) * 256 + k0 + c4 * 4];
            hi.x = tf32r(w.x); hi.y = tf32r(w.y); hi.z = tf32r(w.z); hi.w = tf32r(w.w);
            *(float4*)&sm[PJ_BH + row * PSTR + c4 * 4] = hi;
            if (split) {
                float4 lo;
                lo.x = w.x - hi.x; lo.y = w.y - hi.y; lo.z = w.z - hi.z; lo.w = w.w - hi.w;
                *(float4*)&sm[PJ_BL + row * PSTR + c4 * 4] = lo;
            }
        }
        __syncthreads();
#pragma unroll
        for (int kk = 0; kk < 4; kk++) {
            uint32_t ah[4][4], bh[4][2];
#pragma unroll
            for (int mt = 0; mt < 4; mt++) {
                int r = wm * 64 + mt * 16;
                int i0 = (r + gid) * PSTR + kk * 8 + tid4;
                int i1 = (r + gid + 8) * PSTR + kk * 8 + tid4;
                ah[mt][0] = *(uint32_t*)&sm[PJ_AH + i0];
                ah[mt][1] = *(uint32_t*)&sm[PJ_AH + i1];
                ah[mt][2] = *(uint32_t*)&sm[PJ_AH + i0 + 4];
                ah[mt][3] = *(uint32_t*)&sm[PJ_AH + i1 + 4];
            }
#pragma unroll
            for (int nt = 0; nt < 4; nt++) {
                int n = wn * 32 + nt * 8;
                int i0 = (n + gid) * PSTR + kk * 8 + tid4;
                bh[nt][0] = *(uint32_t*)&sm[PJ_BH + i0];
                bh[nt][1] = *(uint32_t*)&sm[PJ_BH + i0 + 4];
            }
#pragma unroll
            for (int mt = 0; mt < 4; mt++)
#pragma unroll
                for (int nt = 0; nt < 4; nt++)
                    mma8(acc[mt][nt], ah[mt], bh[nt]);
            if (split) {
                uint32_t al[4][4], bl[4][2];
#pragma unroll
                for (int mt = 0; mt < 4; mt++) {
                    int r = wm * 64 + mt * 16;
                    int i0 = (r + gid) * PSTR + kk * 8 + tid4;
                    int i1 = (r + gid + 8) * PSTR + kk * 8 + tid4;
                    al[mt][0] = *(uint32_t*)&sm[PJ_AL + i0];
                    al[mt][1] = *(uint32_t*)&sm[PJ_AL + i1];
                    al[mt][2] = *(uint32_t*)&sm[PJ_AL + i0 + 4];
                    al[mt][3] = *(uint32_t*)&sm[PJ_AL + i1 + 4];
                }
#pragma unroll
                for (int nt = 0; nt < 4; nt++) {
                    int n = wn * 32 + nt * 8;
                    int i0 = (n + gid) * PSTR + kk * 8 + tid4;
                    bl[nt][0] = *(uint32_t*)&sm[PJ_BL + i0];
                    bl[nt][1] = *(uint32_t*)&sm[PJ_BL + i0 + 4];
                }
#pragma unroll
                for (int mt = 0; mt < 4; mt++)
#pragma unroll
                    for (int nt = 0; nt < 4; nt++) {
                        mma8(acc[mt][nt], ah[mt], bl[nt]);
                        mma8(acc[mt][nt], al[mt], bh[nt]);
                    }
            }
        }
        __syncthreads();
    }
#pragma unroll
    for (int mt = 0; mt < 4; mt++)
#pragma unroll
        for (int nt = 0; nt < 4; nt++) {
            int m = m0 + wm * 64 + mt * 16 + gid;
            int n = n0 + wn * 32 + nt * 8 + tid4 * 2;
            dst[(size_t)m * 256 + n]           = acc[mt][nt][0];
            dst[(size_t)m * 256 + n + 1]       = acc[mt][nt][1];
            dst[(size_t)(m + 8) * 256 + n]     = acc[mt][nt][2];
            dst[(size_t)(m + 8) * 256 + n + 1] = acc[mt][nt][3];
        }
}

// ===========================================================================
// Projection kernel B: bf16 m16n8k16 for spatial q/k (sels 0->Qsn, 1->Ksn).
// Standalone so its register budget doesn't pollute the tf32 kernel.
// ===========================================================================
#define PB_SMEM ((128*40 + 256*40) * 2)

__global__ void __launch_bounds__(256) proj_bf16_kernel(
    const float* __restrict__ sh,
    const float* __restrict__ Wq_s, const float* __restrict__ Wk_s)
{
    extern __shared__ __align__(16) char smb[];
    __nv_bfloat16* sA = (__nv_bfloat16*)smb;
    __nv_bfloat16* sB = sA + 128 * 40;
    const int tid = threadIdx.x, wid = tid >> 5, lane = tid & 31;
    const int gid = lane >> 2, tid4 = lane & 3;
    const int wm = wid >> 2, wn = wid & 3;
    const int m0 = blockIdx.x * 128, n0 = blockIdx.y * 128;
    const int sel = blockIdx.z;
    const float* W = (sel == 0) ? Wq_s : Wk_s;
    float* dst = (sel == 0) ? g_Qsn : g_Ksn;

    float acc[4][4][4];
#pragma unroll
    for (int a = 0; a < 4; a++)
#pragma unroll
        for (int b = 0; b < 4; b++)
#pragma unroll
            for (int c = 0; c < 4; c++) acc[a][b][c] = 0.f;

    for (int kc = 0; kc < 8; kc++) {
        const int k0 = kc * 32;
#pragma unroll
        for (int i = 0; i < 4; i++) {
            int f = tid + i * 256;
            int row = f >> 3, c4 = f & 7;
            float4 v = *(const float4*)&sh[(size_t)(m0 + row) * 256 + k0 + c4 * 4];
            uint32_t* dp = (uint32_t*)&sA[row * 40 + c4 * 4];
            dp[0] = packbf(v.x, v.y);
            dp[1] = packbf(v.z, v.w);
        }
#pragma unroll
        for (int i = 0; i < 8; i++) {
            int f = tid + i * 256;
            int row = f >> 3, c4 = f & 7;
            float4 w = *(const float4*)&W[(size_t)(n0 + row) * 256 + k0 + c4 * 4];
            uint32_t* dp = (uint32_t*)&sB[row * 40 + c4 * 4];
            dp[0] = packbf(w.x, w.y);
            dp[1] = packbf(w.z, w.w);
        }
        __syncthreads();
#pragma unroll
        for (int kk2 = 0; kk2 < 2; kk2++) {
            uint32_t a[4][4], bq[4][2];
#pragma unroll
            for (int mt = 0; mt < 4; mt++) {
                int r = wm * 64 + mt * 16;
                const uint32_t* pa = (const uint32_t*)&sA[(r + gid) * 40 + kk2 * 16 + 2 * tid4];
                const uint32_t* pb = (const uint32_t*)&sA[(r + gid + 8) * 40 + kk2 * 16 + 2 * tid4];
                a[mt][0] = pa[0]; a[mt][1] = pb[0];
                a[mt][2] = pa[4]; a[mt][3] = pb[4];
            }
#pragma unroll
            for (int nt = 0; nt < 4; nt++) {
                int n = wn * 32 + nt * 8 + gid;
                const uint32_t* p = (const uint32_t*)&sB[n * 40 + kk2 * 16 + 2 * tid4];
                bq[nt][0] = p[0]; bq[nt][1] = p[4];
            }
#pragma unroll
            for (int mt = 0; mt < 4; mt++)
#pragma unroll
                for (int nt = 0; nt < 4; nt++)
                    mma16(acc[mt][nt], a[mt], bq[nt]);
        }
        __syncthreads();
    }
#pragma unroll
    for (int mt = 0; mt < 4; mt++)
#pragma unroll
        for (int nt = 0; nt < 4; nt++) {
            int m = m0 + wm * 64 + mt * 16 + gid;
            int n = n0 + wn * 32 + nt * 8 + tid4 * 2;
            dst[(size_t)m * 256 + n]           = acc[mt][nt][0];
            dst[(size_t)m * 256 + n + 1]       = acc[mt][nt][1];
            dst[(size_t)(m + 8) * 256 + n]     = acc[mt][nt][2];
            dst[(size_t)(m + 8) * 256 + n + 1] = acc[mt][nt][3];
        }
}

// ===========================================================================
// v_s projection (scalar fp32, K=64)
// ===========================================================================
__global__ __launch_bounds__(256) void vproj_kernel(const float* __restrict__ X,
                                                    const float* __restrict__ W)
{
    __shared__ __align__(16) float Xs[16][68], Ws[16][68];
    const int tid = threadIdx.x, tx = tid & 15, ty = tid >> 4, m0 = blockIdx.x * 64;
    const int lkk = tid & 15, lrow = tid >> 4;
    float acc[4][4];
#pragma unroll
    for (int u = 0; u < 4; u++)
#pragma unroll
        for (int v = 0; v < 4; v++) acc[u][v] = 0.f;
    for (int k0 = 0; k0 < 64; k0 += 16) {
#pragma unroll
        for (int i = 0; i < 4; i++) {
            int row = lrow + i * 16;
            Xs[lkk][row] = X[(m0 + row) * 64 + k0 + lkk];
            Ws[lkk][row] = W[row * 64 + k0 + lkk];
        }
        __syncthreads();
#pragma unroll
        for (int k = 0; k < 16; k++) {
            float4 a = *(const float4*)&Xs[k][ty * 4];
            float4 w = *(const float4*)&Ws[k][tx * 4];
            acc[0][0]+=a.x*w.x; acc[0][1]+=a.x*w.y; acc[0][2]+=a.x*w.z; acc[0][3]+=a.x*w.w;
            acc[1][0]+=a.y*w.x; acc[1][1]+=a.y*w.y; acc[1][2]+=a.y*w.z; acc[1][3]+=a.y*w.w;
            acc[2][0]+=a.z*w.x; acc[2][1]+=a.z*w.y; acc[2][2]+=a.z*w.z; acc[2][3]+=a.z*w.w;
            acc[3][0]+=a.w*w.x; acc[3][1]+=a.w*w.y; acc[3][2]+=a.w*w.z; acc[3][3]+=a.w*w.w;
        }
        __syncthreads();
    }
#pragma unroll
    for (int u = 0; u < 4; u++)
#pragma unroll
        for (int v = 0; v < 4; v++)
            g_Vsn[(size_t)(m0 + ty * 4 + u) * 64 + tx * 4 + v] = acc[u][v];
}

// ===========================================================================
// Channel gram partials via MMA (unchanged)
// ===========================================================================
#define GSTR 36
__global__ void __launch_bounds__(256) chanS_mma_kernel()
{
    __shared__ __align__(16) float Qt[64 * GSTR], Kt[64 * GSTR];
    const int tid = threadIdx.x, wid = tid >> 5, lane = tid & 31;
    const int gid = lane >> 2, tid4 = lane & 3;
    const int wm = wid >> 2, wn = wid & 3;
    const int cid = blockIdx.x, bh = cid >> 3, kc = cid & 7;
    const int b = bh >> 2, h = bh & 3;

    float acc[2][2][4];
#pragma unroll
    for (int a = 0; a < 2; a++)
#pragma unroll
        for (int c = 0; c < 2; c++)
#pragma unroll
            for (int d = 0; d < 4; d++) acc[a][c][d] = 0.f;

    const int lr = tid >> 3;
    const int ch0 = (tid & 7) * 8;

    for (int kt = 0; kt < 8; kt++) {
        int cm = kc * 256 + kt * 32 + lr;
        int r = cm >> 2, t = cm & 3;
        const float* qb = &g_Qc[(size_t)(b * 2048 + h * 512 + r) * 256 + t * 64 + ch0];
        const float* kb = &g_Kc[(size_t)(b * 2048 + h * 512 + r) * 256 + t * 64 + ch0];
        float4 q0 = *(const float4*)qb, q1 = *(const float4*)(qb + 4);
        float4 k0 = *(const float4*)kb, k1 = *(const float4*)(kb + 4);
        Qt[(ch0+0)*GSTR + lr] = tf32r(q0.x); Qt[(ch0+1)*GSTR + lr] = tf32r(q0.y);
        Qt[(ch0+2)*GSTR + lr] = tf32r(q0.z); Qt[(ch0+3)*GSTR + lr] = tf32r(q0.w);
        Qt[(ch0+4)*GSTR + lr] = tf32r(q1.x); Qt[(ch0+5)*GSTR + lr] = tf32r(q1.y);
        Qt[(ch0+6)*GSTR + lr] = tf32r(q1.z); Qt[(ch0+7)*GSTR + lr] = tf32r(q1.w);
        Kt[(ch0+0)*GSTR + lr] = tf32r(k0.x); Kt[(ch0+1)*GSTR + lr] = tf32r(k0.y);
        Kt[(ch0+2)*GSTR + lr] = tf32r(k0.z); Kt[(ch0+3)*GSTR + lr] = tf32r(k0.w);
        Kt[(ch0+4)*GSTR + lr] = tf32r(k1.x); Kt[(ch0+5)*GSTR + lr] = tf32r(k1.y);
        Kt[(ch0+6)*GSTR + lr] = tf32r(k1.z); Kt[(ch0+7)*GSTR + lr] = tf32r(k1.w);
        __syncthreads();
#pragma unroll
        for (int kk = 0; kk < 4; kk++) {
            uint32_t af[2][4], bf[2][2];
#pragma unroll
            for (int mt = 0; mt < 2; mt++) {
                int rI = wm * 32 + mt * 16;
                int i0 = (rI + gid) * GSTR + kk * 8 + tid4;
                int i1 = (rI + gid + 8) * GSTR + kk * 8 + tid4;
                af[mt][0] = *(uint32_t*)&Qt[i0];
                af[mt][1] = *(uint32_t*)&Qt[i1];
                af[mt][2] = *(uint32_t*)&Qt[i0 + 4];
                af[mt][3] = *(uint32_t*)&Qt[i1 + 4];
            }
#pragma unroll
            for (int nt = 0; nt < 2; nt++) {
                int n = wn * 16 + nt * 8;
                int i0 = (n + gid) * GSTR + kk * 8 + tid4;
                bf[nt][0] = *(uint32_t*)&Kt[i0];
                bf[nt][1] = *(uint32_t*)&Kt[i0 + 4];
            }
#pragma unroll
            for (int mt = 0; mt < 2; mt++)
#pragma unroll
                for (int nt = 0; nt < 2; nt++)
                    mma8(acc[mt][nt], af[mt], bf[nt]);
        }
        __syncthreads();
    }
#pragma unroll
    for (int mt = 0; mt < 2; mt++)
#pragma unroll
        for (int nt = 0; nt < 2; nt++) {
            int i = wm * 32 + mt * 16 + gid;
            int j = wn * 16 + nt * 8 + tid4 * 2;
            float* o = &g_Scp[((kc * 16 + bh) << 12)];
            o[i*64 + j]       = acc[mt][nt][0];
            o[i*64 + j + 1]   = acc[mt][nt][1];
            o[(i+8)*64 + j]   = acc[mt][nt][2];
            o[(i+8)*64 + j+1] = acc[mt][nt][3];
        }
}

// ===========================================================================
// x_ca: fused (reduce + softmax) + A@V^T (3-term split).  grid (16,16).
// ===========================================================================
#define XSTR 68
#define XA_HI 0
#define XA_LO (64*XSTR)
#define XB_HI (2*64*XSTR)
#define XB_LO (XB_HI + 128*XSTR)
#define XCA_SMEM ((XB_LO + 128*XSTR) * 4)

__global__ void __launch_bounds__(256) xca_mma_kernel(float* __restrict__ out,
                                                      const float* __restrict__ temp)
{
    extern __shared__ __align__(16) float sm[];
    const int tid = threadIdx.x, wid = tid >> 5, lane = tid & 31;
    const int gid = lane >> 2, tid4 = lane & 3;
    const int wm = wid >> 2, wn = wid & 3;
    const int bh = blockIdx.x, chunk = blockIdx.y, b = bh >> 2, h = bh & 3;
    const float scale = 0.125f * temp[h];

#pragma unroll
    for (int i = 0; i < 16; i++) {
        int e = tid + i * 256;
        float sv = 0.f;
#pragma unroll
        for (int p = 0; p < 8; p++) sv += g_Scp[((p * 16 + bh) << 12) + e];
        sm[XA_HI + (e >> 6) * XSTR + (e & 63)] = sv;
    }
    __syncthreads();
    if (tid < 64) {
        float row[64];
        float sum = 0.f;
#pragma unroll
        for (int j = 0; j < 64; j++) {
            row[j] = __expf(sm[XA_HI + tid * XSTR + j] * scale); sum += row[j];
        }
        float inv = 1.f / sum;
#pragma unroll
        for (int j = 0; j < 64; j++) {
            float a = row[j] * inv;
            float hi = tf32r(a);
            sm[XA_HI + tid * XSTR + j] = hi;
            sm[XA_LO + tid * XSTR + j] = a - hi;
        }
    }
#pragma unroll
    for (int i = 0; i < 8; i++) {
        int f4 = tid + i * 256;
        int lrw = f4 >> 4, c = (f4 & 15) * 4;
        int np = chunk * 128 + lrw;
        int r = np >> 2, t = np & 3;
        float4 v = *(const float4*)&g_Vc[(size_t)(b * 2048 + h * 512 + r) * 256 + t * 64 + c];
        float4 hi, lo;
        hi.x = tf32r(v.x); lo.x = v.x - hi.x; hi.y = tf32r(v.y); lo.y = v.y - hi.y;
        hi.z = tf32r(v.z); lo.z = v.z - hi.z; hi.w = tf32r(v.w); lo.w = v.w - hi.w;
        *(float4*)&sm[XB_HI + lrw * XSTR + c] = hi;
        *(float4*)&sm[XB_LO + lrw * XSTR + c] = lo;
    }
    __syncthreads();

    float acc[2][4][4];
#pragma unroll
    for (int a = 0; a < 2; a++)
#pragma unroll
        for (int c = 0; c < 4; c++)
#pragma unroll
            for (int d = 0; d < 4; d++) acc[a][c][d] = 0.f;

#pragma unroll
    for (int kk = 0; kk < 8; kk++) {
        uint32_t ah[2][4], al[2][4], bh4[4][2], bl4[4][2];
#pragma unroll
        for (int mt = 0; mt < 2; mt++) {
            int rI = wm * 32 + mt * 16;
            int i0 = (rI + gid) * XSTR + kk * 8 + tid4;
            int i1 = (rI + gid + 8) * XSTR + kk * 8 + tid4;
            ah[mt][0] = *(uint32_t*)&sm[XA_HI + i0];
            ah[mt][1] = *(uint32_t*)&sm[XA_HI + i1];
            ah[mt][2] = *(uint32_t*)&sm[XA_HI + i0 + 4];
            ah[mt][3] = *(uint32_t*)&sm[XA_HI + i1 + 4];
            al[mt][0] = *(uint32_t*)&sm[XA_LO + i0];
            al[mt][1] = *(uint32_t*)&sm[XA_LO + i1];
            al[mt][2] = *(uint32_t*)&sm[XA_LO + i0 + 4];
            al[mt][3] = *(uint32_t*)&sm[XA_LO + i1 + 4];
        }
#pragma unroll
        for (int nt = 0; nt < 4; nt++) {
            int n = wn * 32 + nt * 8;
            int i0 = (n + gid) * XSTR + kk * 8 + tid4;
            bh4[nt][0] = *(uint32_t*)&sm[XB_HI + i0];
            bh4[nt][1] = *(uint32_t*)&sm[XB_HI + i0 + 4];
            bl4[nt][0] = *(uint32_t*)&sm[XB_LO + i0];
            bl4[nt][1] = *(uint32_t*)&sm[XB_LO + i0 + 4];
        }
#pragma unroll
        for (int mt = 0; mt < 2; mt++)
#pragma unroll
            for (int nt = 0; nt < 4; nt++) {
                mma8(acc[mt][nt], ah[mt], bh4[nt]);
                mma8(acc[mt][nt], ah[mt], bl4[nt]);
                mma8(acc[mt][nt], al[mt], bh4[nt]);
            }
    }

#pragma unroll
    for (int mt = 0; mt < 2; mt++)
#pragma unroll
        for (int nt = 0; nt < 4; nt++) {
            int dc = wm * 32 + mt * 16 + gid;
            int np = chunk * 128 + wn * 32 + nt * 8 + tid4 * 2;
            int f0 = h * 131072 + dc * 2048 + np;
            *(float2*)&out[(size_t)(b * 2048 + (f0 >> 8)) * 320 + (f0 & 255)] =
                make_float2(acc[mt][nt][0], acc[mt][nt][1]);
            int f1 = f0 + 8 * 2048;
            *(float2*)&out[(size_t)(b * 2048 + (f1 >> 8)) * 320 + (f1 & 255)] =
                make_float2(acc[mt][nt][2], acc[mt][nt][3]);
        }
}

// ===========================================================================
// Spatial flash attention (unchanged from R10 win)
// ===========================================================================
#define SP_Q    0
#define SP_K    18432
#define SP_V    36864
#define SP_RS   41216
#define SP_VP   49408
#define SP_RSUM 53504
#define SP_CSUM 54016
#define SP_OS   0
#define SPAT_SMEM 54080

__global__ void __launch_bounds__(256, 2) spat_mma_kernel(float* __restrict__ out,
                                                          const float* __restrict__ temp2)
{
    extern __shared__ __align__(16) char smc[];
    __nv_bfloat16* sQ = (__nv_bfloat16*)(smc + SP_Q);
    __nv_bfloat16* sK = (__nv_bfloat16*)(smc + SP_K);
    __nv_bfloat16* sV = (__nv_bfloat16*)(smc + SP_V);
    float* RSa   = (float*)(smc + SP_RS);
    float* VPa   = (float*)(smc + SP_VP);
    float* RSUMa = (float*)(smc + SP_RSUM);
    float* CSUMa = (float*)(smc + SP_CSUM);

    const int tid = threadIdx.x, wid = tid >> 5, lane = tid & 31;
    const int gid = lane >> 2, t4 = lane & 3;
    const int wq = wid >> 2, wj = wid & 3;
    const int cid = blockIdx.x, qt = cid & 15, bh = cid >> 4, b = bh >> 2, h = bh & 3;
    const float scale = 0.125f * temp2[h];

    const float4* Qg = (const float4*)(g_Qsn + (size_t)(b * 2048 + h * 512 + qt * 32) * 256);
#pragma unroll
    for (int i = 0; i < 8; i++) {
        int f = tid + i * 256;
        float4 v = Qg[f];
        int q = (f >> 6) * 4 + ((f >> 4) & 3);
        int d = (f & 15) * 4;
        uint32_t* dp = (uint32_t*)&sQ[q * 72 + d];
        dp[0] = packbf(v.x * scale, v.y * scale);
        dp[1] = packbf(v.z * scale, v.w * scale);
    }

    float oc[4][2][4];
#pragma unroll
    for (int a = 0; a < 4; a++)
#pragma unroll
        for (int c = 0; c < 2; c++)
#pragma unroll
            for (int d = 0; d < 4; d++) oc[a][c][d] = 0.f;
    float lpart[8];
#pragma unroll
    for (int j = 0; j < 8; j++) lpart[j] = 0.f;
    float4 vpart = make_float4(0.f, 0.f, 0.f, 0.f);

    for (int t = 0; t < 16; t++) {
        const float4* Kg = (const float4*)(g_Ksn + (size_t)(b * 2048 + h * 512 + t * 32) * 256);
#pragma unroll
        for (int i = 0; i < 8; i++) {
            int f = tid + i * 256;
            float4 v = Kg[f];
            int q = (f >> 6) * 4 + ((f >> 4) & 3);
            int d = (f & 15) * 4;
            uint32_t* dp = (uint32_t*)&sK[q * 72 + d];
            dp[0] = packbf(v.x, v.y);
            dp[1] = packbf(v.z, v.w);
        }
        const float4* Vg = (const float4*)(g_Vsn + (size_t)(b * 2048 + h * 512 + t * 32) * 64);
#pragma unroll
        for (int u = 0; u < 2; u++) {
            int f = tid + u * 256;
            float4 v = Vg[f];
            vpart.x += v.x; vpart.y += v.y; vpart.z += v.z; vpart.w += v.w;
            int j = (f >> 4) * 4 + ((f & 15) >> 2);
            int dv = (f & 3) * 4;
            sV[(dv + 0) * 136 + j] = __float2bfloat16_rn(v.x);
            sV[(dv + 1) * 136 + j] = __float2bfloat16_rn(v.y);
            sV[(dv + 2) * 136 + j] = __float2bfloat16_rn(v.z);
            sV[(dv + 3) * 136 + j] = __float2bfloat16_rn(v.w);
        }
        __syncthreads();

#pragma unroll
        for (int mp = 0; mp < 2; mp++) {
            float accS[2][4][4];
#pragma unroll
            for (int a = 0; a < 2; a++)
#pragma unroll
                for (int c = 0; c < 4; c++)
#pragma unroll
                    for (int d = 0; d < 4; d++) accS[a][c][d] = 0.f;

#pragma unroll
            for (int kk = 0; kk < 4; kk++) {
                uint32_t bK[4][2];
#pragma unroll
                for (int nt = 0; nt < 4; nt++) {
                    int n = wj * 32 + nt * 8 + gid;
                    const uint32_t* p = (const uint32_t*)&sK[n * 72 + kk * 16 + 2 * t4];
                    bK[nt][0] = p[0];
                    bK[nt][1] = p[4];
                }
#pragma unroll
                for (int mi = 0; mi < 2; mi++) {
                    int r = wq * 64 + (mp * 2 + mi) * 16;
                    const uint32_t* pa = (const uint32_t*)&sQ[(r + gid) * 72 + kk * 16 + 2 * t4];
                    const uint32_t* pb = (const uint32_t*)&sQ[(r + gid + 8) * 72 + kk * 16 + 2 * t4];
                    uint32_t a[4] = { pa[0], pb[0], pa[4], pb[4] };
#pragma unroll
                    for (int nt = 0; nt < 4; nt++)
                        mma16(accS[mi][nt], a, bK[nt]);
                }
            }

            uint32_t pA[2][2][4];
#pragma unroll
            for (int mi = 0; mi < 2; mi++) {
#pragma unroll
                for (int nt = 0; nt < 4; nt++) {
                    float pm[4];
#pragma unroll
                    for (int c = 0; c < 4; c++) {
                        float x = accS[mi][nt][c];
                        float tt = fmaf(x, 0.16666667f, 0.5f);
                        tt = fmaf(x, tt, 1.0f);
                        pm[c] = x * tt;
                    }
                    lpart[(mp * 2 + mi) * 2]     += pm[0] + pm[1];
                    lpart[(mp * 2 + mi) * 2 + 1] += pm[2] + pm[3];
                    int kk2 = nt >> 1, half = nt & 1;
                    pA[mi][kk2][half ? 2 : 0] = packbf(pm[0], pm[1]);
                    pA[mi][kk2][half ? 3 : 1] = packbf(pm[2], pm[3]);
                }
            }
#pragma unroll
            for (int kk2 = 0; kk2 < 2; kk2++) {
                uint32_t bV[2][2];
#pragma unroll
                for (int ntv = 0; ntv < 2; ntv++) {
                    const uint32_t* p = (const uint32_t*)&sV[(ntv * 8 + gid) * 136 + wj * 32 + kk2 * 16 + 2 * t4];
                    bV[ntv][0] = p[0];
                    bV[ntv][1] = p[4];
                }
#pragma unroll
                for (int mi = 0; mi < 2; mi++)
#pragma unroll
                    for (int ntv = 0; ntv < 2; ntv++)
                        mma16(oc[mp * 2 + mi][ntv], pA[mi][kk2], bV[ntv]);
            }
        }
        __syncthreads();
    }

#pragma unroll
    for (int j = 0; j < 8; j++) {
        int row = wq * 64 + (j >> 1) * 16 + (j & 1) * 8 + gid;
        RSa[row * 16 + wj * 4 + t4] = lpart[j];
    }
    *(float4*)&VPa[tid * 4] = vpart;
    float* OS = (float*)(smc + SP_OS);
#pragma unroll
    for (int mt = 0; mt < 4; mt++)
#pragma unroll
        for (int ntv = 0; ntv < 2; ntv++) {
            int r = wq * 64 + mt * 16 + gid;
            *(float2*)&OS[wj * 2048 + r * 16 + ntv * 8 + 2 * t4] =
                make_float2(oc[mt][ntv][0], oc[mt][ntv][1]);
            *(float2*)&OS[wj * 2048 + (r + 8) * 16 + ntv * 8 + 2 * t4] =
                make_float2(oc[mt][ntv][2], oc[mt][ntv][3]);
        }
    __syncthreads();
    if (tid < 128) {
        float a = 0.f;
#pragma unroll
        for (int i = 0; i < 16; i++) a += RSa[tid * 16 + i];
        RSUMa[tid] = 2048.0f + a;
    }
    if (tid < 16) {
        int g = tid >> 2, comp = tid & 3;
        float a = 0.f;
        for (int j = 0; j < 64; j++) a += VPa[(j * 4 + g) * 4 + comp];
        CSUMa[tid] = a;
    }
    __syncthreads();

    const int row = tid >> 1, c0 = (tid & 1) * 8;
    const float inv = 1.f / RSUMa[row];
    float x[8];
#pragma unroll
    for (int i = 0; i < 8; i++) {
        float o = CSUMa[c0 + i];
#pragma unroll
        for (int w = 0; w < 4; w++) o += OS[w * 2048 + row * 16 + c0 + i];
        x[i] = o * inv;
    }
    const int n = qt * 128 + row;
    const int f0 = h * 32768 + n * 16 + c0;
    float* og = out + (size_t)(b * 2048 + (f0 >> 6)) * 320 + 256 + (f0 & 63);
    *(float4*)&og[0] = make_float4(x[0], x[1], x[2], x[3]);
    *(float4*)&og[4] = make_float4(x[4], x[5], x[6], x[7]);
}

// ===========================================================================
// Launcher
// ===========================================================================
extern "C" void kernel_launch(void* const* d_in, const int* in_sizes, int n_in,
                              void* d_out, int out_size)
{
    const float* s     = (const float*)d_in[0];
    const float* h     = (const float*)d_in[1];
    const float* sh    = (const float*)d_in[2];
    const float* temp  = (const float*)d_in[3];
    const float* temp2 = (const float*)d_in[4];
    const float* Wq_c  = (const float*)d_in[5];
    const float* Wq_s  = (const float*)d_in[6];
    const float* Wk_c  = (const float*)d_in[7];
    const float* Wv_c  = (const float*)d_in[8];
    const float* Wk_s  = (const float*)d_in[9];
    const float* Wv_s  = (const float*)d_in[10];
    float* out = (float*)d_out;

    cudaFuncSetAttribute(proj_tf32_kernel, cudaFuncAttributeMaxDynamicSharedMemorySize, PJ_SMEM);
    cudaFuncSetAttribute(proj_bf16_kernel, cudaFuncAttributeMaxDynamicSharedMemorySize, PB_SMEM);
    cudaFuncSetAttribute(xca_mma_kernel,  cudaFuncAttributeMaxDynamicSharedMemorySize, XCA_SMEM);
    cudaFuncSetAttribute(spat_mma_kernel, cudaFuncAttributeMaxDynamicSharedMemorySize, SPAT_SMEM);

    proj_bf16_kernel<<<dim3(64, 2, 2), 256, PB_SMEM>>>(sh, Wq_s, Wk_s);
    proj_tf32_kernel<<<dim3(64, 2, 3), 256, PJ_SMEM>>>(s, sh, Wq_c, Wk_c, Wv_c);
    vproj_kernel<<<128, 256>>>(h, Wv_s);
    chanS_mma_kernel<<<128, 256>>>();
    xca_mma_kernel<<<dim3(16, 16), 256, XCA_SMEM>>>(out, temp);
    spat_mma_kernel<<<256, 256, SPAT_SMEM>>>(out, temp2);
}

// round 14
// speedup vs baseline: 1.0423x; 1.0331x over previous
#include <cuda_runtime.h>
#include <cuda_bf16.h>
#include <cstdint>
#include <math.h>

// ---------------------------------------------------------------------------
// Scratch
// ---------------------------------------------------------------------------
__device__ float g_Qc [4*2048*256];
__device__ float g_Kc [4*2048*256];
__device__ float g_Vc [4*2048*256];
__device__ float g_Qsn[4*2048*256];
__device__ float g_Ksn[4*2048*256];
__device__ float g_Vsn[4*2048*64];
__device__ float g_Scp[16*16*64*64];  // channel gram partials [kc][bh][64*64]

// ---------------------------------------------------------------------------
// warp MMA helpers
// ---------------------------------------------------------------------------
__device__ __forceinline__ void mma8(float* c, const uint32_t* a, const uint32_t* b) {
    asm volatile("mma.sync.aligned.m16n8k8.row.col.f32.tf32.tf32.f32 "
        "{%0,%1,%2,%3}, {%4,%5,%6,%7}, {%8,%9}, {%0,%1,%2,%3};"
        : "+f"(c[0]), "+f"(c[1]), "+f"(c[2]), "+f"(c[3])
        : "r"(a[0]), "r"(a[1]), "r"(a[2]), "r"(a[3]), "r"(b[0]), "r"(b[1]));
}
__device__ __forceinline__ void mma16(float* c, const uint32_t* a, const uint32_t* b) {
    asm volatile("mma.sync.aligned.m16n8k16.row.col.f32.bf16.bf16.f32 "
        "{%0,%1,%2,%3}, {%4,%5,%6,%7}, {%8,%9}, {%0,%1,%2,%3};"
        : "+f"(c[0]), "+f"(c[1]), "+f"(c[2]), "+f"(c[3])
        : "r"(a[0]), "r"(a[1]), "r"(a[2]), "r"(a[3]), "r"(b[0]), "r"(b[1]));
}
__device__ __forceinline__ float tf32r(float x) {
    uint32_t u; asm("cvt.rna.tf32.f32 %0, %1;" : "=r"(u) : "f"(x));
    return __uint_as_float(u);
}
// pack (e0 -> low half, e1 -> high half)
__device__ __forceinline__ uint32_t packbf(float e0, float e1) {
    uint32_t r; asm("cvt.rn.bf16x2.f32 %0, %1, %2;" : "=r"(r) : "f"(e1), "f"(e0));
    return r;
}

// ===========================================================================
// Projections: R10 configuration (all tf32; 3-term split only for Wv_c).
// grid (64, 2, 5), one launch.
// ===========================================================================
#define PSTR 36
#define PJ_AH 0
#define PJ_AL (128*PSTR)
#define PJ_BH (2*128*PSTR)
#define PJ_BL (3*128*PSTR)
#define PJ_SMEM (4*128*PSTR*4)

__global__ void __launch_bounds__(256) proj_mma_kernel(
    const float* __restrict__ s, const float* __restrict__ sh,
    const float* __restrict__ Wq_c, const float* __restrict__ Wk_c,
    const float* __restrict__ Wv_c, const float* __restrict__ Wq_s,
    const float* __restrict__ Wk_s)
{
    extern __shared__ __align__(16) float sm[];
    const int tid = threadIdx.x, wid = tid >> 5, lane = tid & 31;
    const int gid = lane >> 2, tid4 = lane & 3;
    const int wm = wid >> 2, wn = wid & 3;
    const int m0 = blockIdx.x * 128, n0 = blockIdx.y * 128;
    const int sel = blockIdx.z;
    const bool split = (sel == 2);

    const float* X = (sel == 0) ? s : sh;
    const float* W = (sel == 0) ? Wq_c : (sel == 1) ? Wk_c : (sel == 2) ? Wv_c
                   : (sel == 3) ? Wq_s : Wk_s;
    float* dst = (sel == 0) ? g_Qc : (sel == 1) ? g_Kc : (sel == 2) ? g_Vc
               : (sel == 3) ? g_Qsn : g_Ksn;

    float acc[4][4][4];
#pragma unroll
    for (int a = 0; a < 4; a++)
#pragma unroll
        for (int b = 0; b < 4; b++)
#pragma unroll
            for (int c = 0; c < 4; c++) acc[a][b][c] = 0.f;

    for (int kc = 0; kc < 8; kc++) {
        const int k0 = kc * 32;
#pragma unroll
        for (int i = 0; i < 4; i++) {
            int f = tid + i * 256;
            int row = f >> 3, c4 = f & 7;
            float4 v = *(const float4*)&X[(size_t)(m0 + row) * 256 + k0 + c4 * 4];
            float4 hi;
            hi.x = tf32r(v.x); hi.y = tf32r(v.y); hi.z = tf32r(v.z); hi.w = tf32r(v.w);
            *(float4*)&sm[PJ_AH + row * PSTR + c4 * 4] = hi;
            if (split) {
                float4 lo;
                lo.x = v.x - hi.x; lo.y = v.y - hi.y; lo.z = v.z - hi.z; lo.w = v.w - hi.w;
                *(float4*)&sm[PJ_AL + row * PSTR + c4 * 4] = lo;
            }
            float4 w = *(const float4*)&W[(size_t)(n0 + row) * 256 + k0 + c4 * 4];
            hi.x = tf32r(w.x); hi.y = tf32r(w.y); hi.z = tf32r(w.z); hi.w = tf32r(w.w);
            *(float4*)&sm[PJ_BH + row * PSTR + c4 * 4] = hi;
            if (split) {
                float4 lo;
                lo.x = w.x - hi.x; lo.y = w.y - hi.y; lo.z = w.z - hi.z; lo.w = w.w - hi.w;
                *(float4*)&sm[PJ_BL + row * PSTR + c4 * 4] = lo;
            }
        }
        __syncthreads();
#pragma unroll
        for (int kk = 0; kk < 4; kk++) {
            uint32_t ah[4][4], bh[4][2];
#pragma unroll
            for (int mt = 0; mt < 4; mt++) {
                int r = wm * 64 + mt * 16;
                int i0 = (r + gid) * PSTR + kk * 8 + tid4;
                int i1 = (r + gid + 8) * PSTR + kk * 8 + tid4;
                ah[mt][0] = *(uint32_t*)&sm[PJ_AH + i0];
                ah[mt][1] = *(uint32_t*)&sm[PJ_AH + i1];
                ah[mt][2] = *(uint32_t*)&sm[PJ_AH + i0 + 4];
                ah[mt][3] = *(uint32_t*)&sm[PJ_AH + i1 + 4];
            }
#pragma unroll
            for (int nt = 0; nt < 4; nt++) {
                int n = wn * 32 + nt * 8;
                int i0 = (n + gid) * PSTR + kk * 8 + tid4;
                bh[nt][0] = *(uint32_t*)&sm[PJ_BH + i0];
                bh[nt][1] = *(uint32_t*)&sm[PJ_BH + i0 + 4];
            }
#pragma unroll
            for (int mt = 0; mt < 4; mt++)
#pragma unroll
                for (int nt = 0; nt < 4; nt++)
                    mma8(acc[mt][nt], ah[mt], bh[nt]);
            if (split) {
                uint32_t al[4][4], bl[4][2];
#pragma unroll
                for (int mt = 0; mt < 4; mt++) {
                    int r = wm * 64 + mt * 16;
                    int i0 = (r + gid) * PSTR + kk * 8 + tid4;
                    int i1 = (r + gid + 8) * PSTR + kk * 8 + tid4;
                    al[mt][0] = *(uint32_t*)&sm[PJ_AL + i0];
                    al[mt][1] = *(uint32_t*)&sm[PJ_AL + i1];
                    al[mt][2] = *(uint32_t*)&sm[PJ_AL + i0 + 4];
                    al[mt][3] = *(uint32_t*)&sm[PJ_AL + i1 + 4];
                }
#pragma unroll
                for (int nt = 0; nt < 4; nt++) {
                    int n = wn * 32 + nt * 8;
                    int i0 = (n + gid) * PSTR + kk * 8 + tid4;
                    bl[nt][0] = *(uint32_t*)&sm[PJ_BL + i0];
                    bl[nt][1] = *(uint32_t*)&sm[PJ_BL + i0 + 4];
                }
#pragma unroll
                for (int mt = 0; mt < 4; mt++)
#pragma unroll
                    for (int nt = 0; nt < 4; nt++) {
                        mma8(acc[mt][nt], ah[mt], bl[nt]);
                        mma8(acc[mt][nt], al[mt], bh[nt]);
                    }
            }
        }
        __syncthreads();
    }
#pragma unroll
    for (int mt = 0; mt < 4; mt++)
#pragma unroll
        for (int nt = 0; nt < 4; nt++) {
            int m = m0 + wm * 64 + mt * 16 + gid;
            int n = n0 + wn * 32 + nt * 8 + tid4 * 2;
            dst[(size_t)m * 256 + n]           = acc[mt][nt][0];
            dst[(size_t)m * 256 + n + 1]       = acc[mt][nt][1];
            dst[(size_t)(m + 8) * 256 + n]     = acc[mt][nt][2];
            dst[(size_t)(m + 8) * 256 + n + 1] = acc[mt][nt][3];
        }
}

// ===========================================================================
// v_s projection (scalar fp32, K=64)
// ===========================================================================
__global__ __launch_bounds__(256) void vproj_kernel(const float* __restrict__ X,
                                                    const float* __restrict__ W)
{
    __shared__ __align__(16) float Xs[16][68], Ws[16][68];
    const int tid = threadIdx.x, tx = tid & 15, ty = tid >> 4, m0 = blockIdx.x * 64;
    const int lkk = tid & 15, lrow = tid >> 4;
    float acc[4][4];
#pragma unroll
    for (int u = 0; u < 4; u++)
#pragma unroll
        for (int v = 0; v < 4; v++) acc[u][v] = 0.f;
    for (int k0 = 0; k0 < 64; k0 += 16) {
#pragma unroll
        for (int i = 0; i < 4; i++) {
            int row = lrow + i * 16;
            Xs[lkk][row] = X[(m0 + row) * 64 + k0 + lkk];
            Ws[lkk][row] = W[row * 64 + k0 + lkk];
        }
        __syncthreads();
#pragma unroll
        for (int k = 0; k < 16; k++) {
            float4 a = *(const float4*)&Xs[k][ty * 4];
            float4 w = *(const float4*)&Ws[k][tx * 4];
            acc[0][0]+=a.x*w.x; acc[0][1]+=a.x*w.y; acc[0][2]+=a.x*w.z; acc[0][3]+=a.x*w.w;
            acc[1][0]+=a.y*w.x; acc[1][1]+=a.y*w.y; acc[1][2]+=a.y*w.z; acc[1][3]+=a.y*w.w;
            acc[2][0]+=a.z*w.x; acc[2][1]+=a.z*w.y; acc[2][2]+=a.z*w.z; acc[2][3]+=a.z*w.w;
            acc[3][0]+=a.w*w.x; acc[3][1]+=a.w*w.y; acc[3][2]+=a.w*w.z; acc[3][3]+=a.w*w.w;
        }
        __syncthreads();
    }
#pragma unroll
    for (int u = 0; u < 4; u++)
#pragma unroll
        for (int v = 0; v < 4; v++)
            g_Vsn[(size_t)(m0 + ty * 4 + u) * 64 + tx * 4 + v] = acc[u][v];
}

// ===========================================================================
// Channel gram partials: GSTR 37 (2-way instead of 8-way store conflicts),
// grid 256 = (bh*16 + kc), 128 composite rows per CTA (4 tiles of 32).
// ===========================================================================
#define GSTR 37
__global__ void __launch_bounds__(256) chanS_mma_kernel()
{
    __shared__ __align__(16) float Qt[64 * GSTR], Kt[64 * GSTR];
    const int tid = threadIdx.x, wid = tid >> 5, lane = tid & 31;
    const int gid = lane >> 2, tid4 = lane & 3;
    const int wm = wid >> 2, wn = wid & 3;
    const int cid = blockIdx.x, bh = cid >> 4, kc = cid & 15;
    const int b = bh >> 2, h = bh & 3;

    float acc[2][2][4];
#pragma unroll
    for (int a = 0; a < 2; a++)
#pragma unroll
        for (int c = 0; c < 2; c++)
#pragma unroll
            for (int d = 0; d < 4; d++) acc[a][c][d] = 0.f;

    const int lr = tid >> 3;
    const int ch0 = (tid & 7) * 8;

    for (int kt = 0; kt < 4; kt++) {
        int cm = kc * 128 + kt * 32 + lr;
        int r = cm >> 2, t = cm & 3;
        const float* qb = &g_Qc[(size_t)(b * 2048 + h * 512 + r) * 256 + t * 64 + ch0];
        const float* kb = &g_Kc[(size_t)(b * 2048 + h * 512 + r) * 256 + t * 64 + ch0];
        float4 q0 = *(const float4*)qb, q1 = *(const float4*)(qb + 4);
        float4 k0 = *(const float4*)kb, k1 = *(const float4*)(kb + 4);
        Qt[(ch0+0)*GSTR + lr] = tf32r(q0.x); Qt[(ch0+1)*GSTR + lr] = tf32r(q0.y);
        Qt[(ch0+2)*GSTR + lr] = tf32r(q0.z); Qt[(ch0+3)*GSTR + lr] = tf32r(q0.w);
        Qt[(ch0+4)*GSTR + lr] = tf32r(q1.x); Qt[(ch0+5)*GSTR + lr] = tf32r(q1.y);
        Qt[(ch0+6)*GSTR + lr] = tf32r(q1.z); Qt[(ch0+7)*GSTR + lr] = tf32r(q1.w);
        Kt[(ch0+0)*GSTR + lr] = tf32r(k0.x); Kt[(ch0+1)*GSTR + lr] = tf32r(k0.y);
        Kt[(ch0+2)*GSTR + lr] = tf32r(k0.z); Kt[(ch0+3)*GSTR + lr] = tf32r(k0.w);
        Kt[(ch0+4)*GSTR + lr] = tf32r(k1.x); Kt[(ch0+5)*GSTR + lr] = tf32r(k1.y);
        Kt[(ch0+6)*GSTR + lr] = tf32r(k1.z); Kt[(ch0+7)*GSTR + lr] = tf32r(k1.w);
        __syncthreads();
#pragma unroll
        for (int kk = 0; kk < 4; kk++) {
            uint32_t af[2][4], bf[2][2];
#pragma unroll
            for (int mt = 0; mt < 2; mt++) {
                int rI = wm * 32 + mt * 16;
                int i0 = (rI + gid) * GSTR + kk * 8 + tid4;
                int i1 = (rI + gid + 8) * GSTR + kk * 8 + tid4;
                af[mt][0] = *(uint32_t*)&Qt[i0];
                af[mt][1] = *(uint32_t*)&Qt[i1];
                af[mt][2] = *(uint32_t*)&Qt[i0 + 4];
                af[mt][3] = *(uint32_t*)&Qt[i1 + 4];
            }
#pragma unroll
            for (int nt = 0; nt < 2; nt++) {
                int n = wn * 16 + nt * 8;
                int i0 = (n + gid) * GSTR + kk * 8 + tid4;
                bf[nt][0] = *(uint32_t*)&Kt[i0];
                bf[nt][1] = *(uint32_t*)&Kt[i0 + 4];
            }
#pragma unroll
            for (int mt = 0; mt < 2; mt++)
#pragma unroll
                for (int nt = 0; nt < 2; nt++)
                    mma8(acc[mt][nt], af[mt], bf[nt]);
        }
        __syncthreads();
    }
#pragma unroll
    for (int mt = 0; mt < 2; mt++)
#pragma unroll
        for (int nt = 0; nt < 2; nt++) {
            int i = wm * 32 + mt * 16 + gid;
            int j = wn * 16 + nt * 8 + tid4 * 2;
            float* o = &g_Scp[((kc * 16 + bh) << 12)];
            o[i*64 + j]       = acc[mt][nt][0];
            o[i*64 + j + 1]   = acc[mt][nt][1];
            o[(i+8)*64 + j]   = acc[mt][nt][2];
            o[(i+8)*64 + j+1] = acc[mt][nt][3];
        }
}

// ===========================================================================
// x_ca: fused (reduce 16 partials + softmax) + A@V^T (3-term split).
// grid (16, 16).
// ===========================================================================
#define XSTR 68
#define XA_HI 0
#define XA_LO (64*XSTR)
#define XB_HI (2*64*XSTR)
#define XB_LO (XB_HI + 128*XSTR)
#define XCA_SMEM ((XB_LO + 128*XSTR) * 4)

__global__ void __launch_bounds__(256) xca_mma_kernel(float* __restrict__ out,
                                                      const float* __restrict__ temp)
{
    extern __shared__ __align__(16) float sm[];
    const int tid = threadIdx.x, wid = tid >> 5, lane = tid & 31;
    const int gid = lane >> 2, tid4 = lane & 3;
    const int wm = wid >> 2, wn = wid & 3;
    const int bh = blockIdx.x, chunk = blockIdx.y, b = bh >> 2, h = bh & 3;
    const float scale = 0.125f * temp[h];

#pragma unroll
    for (int i = 0; i < 16; i++) {
        int e = tid + i * 256;
        float sv = 0.f;
#pragma unroll
        for (int p = 0; p < 16; p++) sv += g_Scp[((p * 16 + bh) << 12) + e];
        sm[XA_HI + (e >> 6) * XSTR + (e & 63)] = sv;
    }
    __syncthreads();
    if (tid < 64) {
        float row[64];
        float sum = 0.f;
#pragma unroll
        for (int j = 0; j < 64; j++) {
            row[j] = __expf(sm[XA_HI + tid * XSTR + j] * scale); sum += row[j];
        }
        float inv = 1.f / sum;
#pragma unroll
        for (int j = 0; j < 64; j++) {
            float a = row[j] * inv;
            float hi = tf32r(a);
            sm[XA_HI + tid * XSTR + j] = hi;
            sm[XA_LO + tid * XSTR + j] = a - hi;
        }
    }
#pragma unroll
    for (int i = 0; i < 8; i++) {
        int f4 = tid + i * 256;
        int lrw = f4 >> 4, c = (f4 & 15) * 4;
        int np = chunk * 128 + lrw;
        int r = np >> 2, t = np & 3;
        float4 v = *(const float4*)&g_Vc[(size_t)(b * 2048 + h * 512 + r) * 256 + t * 64 + c];
        float4 hi, lo;
        hi.x = tf32r(v.x); lo.x = v.x - hi.x; hi.y = tf32r(v.y); lo.y = v.y - hi.y;
        hi.z = tf32r(v.z); lo.z = v.z - hi.z; hi.w = tf32r(v.w); lo.w = v.w - hi.w;
        *(float4*)&sm[XB_HI + lrw * XSTR + c] = hi;
        *(float4*)&sm[XB_LO + lrw * XSTR + c] = lo;
    }
    __syncthreads();

    float acc[2][4][4];
#pragma unroll
    for (int a = 0; a < 2; a++)
#pragma unroll
        for (int c = 0; c < 4; c++)
#pragma unroll
            for (int d = 0; d < 4; d++) acc[a][c][d] = 0.f;

#pragma unroll
    for (int kk = 0; kk < 8; kk++) {
        uint32_t ah[2][4], al[2][4], bh4[4][2], bl4[4][2];
#pragma unroll
        for (int mt = 0; mt < 2; mt++) {
            int rI = wm * 32 + mt * 16;
            int i0 = (rI + gid) * XSTR + kk * 8 + tid4;
            int i1 = (rI + gid + 8) * XSTR + kk * 8 + tid4;
            ah[mt][0] = *(uint32_t*)&sm[XA_HI + i0];
            ah[mt][1] = *(uint32_t*)&sm[XA_HI + i1];
            ah[mt][2] = *(uint32_t*)&sm[XA_HI + i0 + 4];
            ah[mt][3] = *(uint32_t*)&sm[XA_HI + i1 + 4];
            al[mt][0] = *(uint32_t*)&sm[XA_LO + i0];
            al[mt][1] = *(uint32_t*)&sm[XA_LO + i1];
            al[mt][2] = *(uint32_t*)&sm[XA_LO + i0 + 4];
            al[mt][3] = *(uint32_t*)&sm[XA_LO + i1 + 4];
        }
#pragma unroll
        for (int nt = 0; nt < 4; nt++) {
            int n = wn * 32 + nt * 8;
            int i0 = (n + gid) * XSTR + kk * 8 + tid4;
            bh4[nt][0] = *(uint32_t*)&sm[XB_HI + i0];
            bh4[nt][1] = *(uint32_t*)&sm[XB_HI + i0 + 4];
            bl4[nt][0] = *(uint32_t*)&sm[XB_LO + i0];
            bl4[nt][1] = *(uint32_t*)&sm[XB_LO + i0 + 4];
        }
#pragma unroll
        for (int mt = 0; mt < 2; mt++)
#pragma unroll
            for (int nt = 0; nt < 4; nt++) {
                mma8(acc[mt][nt], ah[mt], bh4[nt]);
                mma8(acc[mt][nt], ah[mt], bl4[nt]);
                mma8(acc[mt][nt], al[mt], bh4[nt]);
            }
    }

#pragma unroll
    for (int mt = 0; mt < 2; mt++)
#pragma unroll
        for (int nt = 0; nt < 4; nt++) {
            int dc = wm * 32 + mt * 16 + gid;
            int np = chunk * 128 + wn * 32 + nt * 8 + tid4 * 2;
            int f0 = h * 131072 + dc * 2048 + np;
            *(float2*)&out[(size_t)(b * 2048 + (f0 >> 8)) * 320 + (f0 & 255)] =
                make_float2(acc[mt][nt][0], acc[mt][nt][1]);
            int f1 = f0 + 8 * 2048;
            *(float2*)&out[(size_t)(b * 2048 + (f1 >> 8)) * 320 + (f1 & 255)] =
                make_float2(acc[mt][nt][2], acc[mt][nt][3]);
        }
}

// ===========================================================================
// Spatial flash attention (unchanged from R10 win)
// ===========================================================================
#define SP_Q    0
#define SP_K    18432
#define SP_V    36864
#define SP_RS   41216
#define SP_VP   49408
#define SP_RSUM 53504
#define SP_CSUM 54016
#define SP_OS   0
#define SPAT_SMEM 54080

__global__ void __launch_bounds__(256, 2) spat_mma_kernel(float* __restrict__ out,
                                                          const float* __restrict__ temp2)
{
    extern __shared__ __align__(16) char smc[];
    __nv_bfloat16* sQ = (__nv_bfloat16*)(smc + SP_Q);
    __nv_bfloat16* sK = (__nv_bfloat16*)(smc + SP_K);
    __nv_bfloat16* sV = (__nv_bfloat16*)(smc + SP_V);
    float* RSa   = (float*)(smc + SP_RS);
    float* VPa   = (float*)(smc + SP_VP);
    float* RSUMa = (float*)(smc + SP_RSUM);
    float* CSUMa = (float*)(smc + SP_CSUM);

    const int tid = threadIdx.x, wid = tid >> 5, lane = tid & 31;
    const int gid = lane >> 2, t4 = lane & 3;
    const int wq = wid >> 2, wj = wid & 3;
    const int cid = blockIdx.x, qt = cid & 15, bh = cid >> 4, b = bh >> 2, h = bh & 3;
    const float scale = 0.125f * temp2[h];

    const float4* Qg = (const float4*)(g_Qsn + (size_t)(b * 2048 + h * 512 + qt * 32) * 256);
#pragma unroll
    for (int i = 0; i < 8; i++) {
        int f = tid + i * 256;
        float4 v = Qg[f];
        int q = (f >> 6) * 4 + ((f >> 4) & 3);
        int d = (f & 15) * 4;
        uint32_t* dp = (uint32_t*)&sQ[q * 72 + d];
        dp[0] = packbf(v.x * scale, v.y * scale);
        dp[1] = packbf(v.z * scale, v.w * scale);
    }

    float oc[4][2][4];
#pragma unroll
    for (int a = 0; a < 4; a++)
#pragma unroll
        for (int c = 0; c < 2; c++)
#pragma unroll
            for (int d = 0; d < 4; d++) oc[a][c][d] = 0.f;
    float lpart[8];
#pragma unroll
    for (int j = 0; j < 8; j++) lpart[j] = 0.f;
    float4 vpart = make_float4(0.f, 0.f, 0.f, 0.f);

    for (int t = 0; t < 16; t++) {
        const float4* Kg = (const float4*)(g_Ksn + (size_t)(b * 2048 + h * 512 + t * 32) * 256);
#pragma unroll
        for (int i = 0; i < 8; i++) {
            int f = tid + i * 256;
            float4 v = Kg[f];
            int q = (f >> 6) * 4 + ((f >> 4) & 3);
            int d = (f & 15) * 4;
            uint32_t* dp = (uint32_t*)&sK[q * 72 + d];
            dp[0] = packbf(v.x, v.y);
            dp[1] = packbf(v.z, v.w);
        }
        const float4* Vg = (const float4*)(g_Vsn + (size_t)(b * 2048 + h * 512 + t * 32) * 64);
#pragma unroll
        for (int u = 0; u < 2; u++) {
            int f = tid + u * 256;
            float4 v = Vg[f];
            vpart.x += v.x; vpart.y += v.y; vpart.z += v.z; vpart.w += v.w;
            int j = (f >> 4) * 4 + ((f & 15) >> 2);
            int dv = (f & 3) * 4;
            sV[(dv + 0) * 136 + j] = __float2bfloat16_rn(v.x);
            sV[(dv + 1) * 136 + j] = __float2bfloat16_rn(v.y);
            sV[(dv + 2) * 136 + j] = __float2bfloat16_rn(v.z);
            sV[(dv + 3) * 136 + j] = __float2bfloat16_rn(v.w);
        }
        __syncthreads();

#pragma unroll
        for (int mp = 0; mp < 2; mp++) {
            float accS[2][4][4];
#pragma unroll
            for (int a = 0; a < 2; a++)
#pragma unroll
                for (int c = 0; c < 4; c++)
#pragma unroll
                    for (int d = 0; d < 4; d++) accS[a][c][d] = 0.f;

#pragma unroll
            for (int kk = 0; kk < 4; kk++) {
                uint32_t bK[4][2];
#pragma unroll
                for (int nt = 0; nt < 4; nt++) {
                    int n = wj * 32 + nt * 8 + gid;
                    const uint32_t* p = (const uint32_t*)&sK[n * 72 + kk * 16 + 2 * t4];
                    bK[nt][0] = p[0];
                    bK[nt][1] = p[4];
                }
#pragma unroll
                for (int mi = 0; mi < 2; mi++) {
                    int r = wq * 64 + (mp * 2 + mi) * 16;
                    const uint32_t* pa = (const uint32_t*)&sQ[(r + gid) * 72 + kk * 16 + 2 * t4];
                    const uint32_t* pb = (const uint32_t*)&sQ[(r + gid + 8) * 72 + kk * 16 + 2 * t4];
                    uint32_t a[4] = { pa[0], pb[0], pa[4], pb[4] };
#pragma unroll
                    for (int nt = 0; nt < 4; nt++)
                        mma16(accS[mi][nt], a, bK[nt]);
                }
            }

            uint32_t pA[2][2][4];
#pragma unroll
            for (int mi = 0; mi < 2; mi++) {
#pragma unroll
                for (int nt = 0; nt < 4; nt++) {
                    float pm[4];
#pragma unroll
                    for (int c = 0; c < 4; c++) {
                        float x = accS[mi][nt][c];
                        float tt = fmaf(x, 0.16666667f, 0.5f);
                        tt = fmaf(x, tt, 1.0f);
                        pm[c] = x * tt;
                    }
                    lpart[(mp * 2 + mi) * 2]     += pm[0] + pm[1];
                    lpart[(mp * 2 + mi) * 2 + 1] += pm[2] + pm[3];
                    int kk2 = nt >> 1, half = nt & 1;
                    pA[mi][kk2][half ? 2 : 0] = packbf(pm[0], pm[1]);
                    pA[mi][kk2][half ? 3 : 1] = packbf(pm[2], pm[3]);
                }
            }
#pragma unroll
            for (int kk2 = 0; kk2 < 2; kk2++) {
                uint32_t bV[2][2];
#pragma unroll
                for (int ntv = 0; ntv < 2; ntv++) {
                    const uint32_t* p = (const uint32_t*)&sV[(ntv * 8 + gid) * 136 + wj * 32 + kk2 * 16 + 2 * t4];
                    bV[ntv][0] = p[0];
                    bV[ntv][1] = p[4];
                }
#pragma unroll
                for (int mi = 0; mi < 2; mi++)
#pragma unroll
                    for (int ntv = 0; ntv < 2; ntv++)
                        mma16(oc[mp * 2 + mi][ntv], pA[mi][kk2], bV[ntv]);
            }
        }
        __syncthreads();
    }

#pragma unroll
    for (int j = 0; j < 8; j++) {
        int row = wq * 64 + (j >> 1) * 16 + (j & 1) * 8 + gid;
        RSa[row * 16 + wj * 4 + t4] = lpart[j];
    }
    *(float4*)&VPa[tid * 4] = vpart;
    float* OS = (float*)(smc + SP_OS);
#pragma unroll
    for (int mt = 0; mt < 4; mt++)
#pragma unroll
        for (int ntv = 0; ntv < 2; ntv++) {
            int r = wq * 64 + mt * 16 + gid;
            *(float2*)&OS[wj * 2048 + r * 16 + ntv * 8 + 2 * t4] =
                make_float2(oc[mt][ntv][0], oc[mt][ntv][1]);
            *(float2*)&OS[wj * 2048 + (r + 8) * 16 + ntv * 8 + 2 * t4] =
                make_float2(oc[mt][ntv][2], oc[mt][ntv][3]);
        }
    __syncthreads();
    if (tid < 128) {
        float a = 0.f;
#pragma unroll
        for (int i = 0; i < 16; i++) a += RSa[tid * 16 + i];
        RSUMa[tid] = 2048.0f + a;
    }
    if (tid < 16) {
        int g = tid >> 2, comp = tid & 3;
        float a = 0.f;
        for (int j = 0; j < 64; j++) a += VPa[(j * 4 + g) * 4 + comp];
        CSUMa[tid] = a;
    }
    __syncthreads();

    const int row = tid >> 1, c0 = (tid & 1) * 8;
    const float inv = 1.f / RSUMa[row];
    float x[8];
#pragma unroll
    for (int i = 0; i < 8; i++) {
        float o = CSUMa[c0 + i];
#pragma unroll
        for (int w = 0; w < 4; w++) o += OS[w * 2048 + row * 16 + c0 + i];
        x[i] = o * inv;
    }
    const int n = qt * 128 + row;
    const int f0 = h * 32768 + n * 16 + c0;
    float* og = out + (size_t)(b * 2048 + (f0 >> 6)) * 320 + 256 + (f0 & 63);
    *(float4*)&og[0] = make_float4(x[0], x[1], x[2], x[3]);
    *(float4*)&og[4] = make_float4(x[4], x[5], x[6], x[7]);
}

// ===========================================================================
// Launcher
// ===========================================================================
extern "C" void kernel_launch(void* const* d_in, const int* in_sizes, int n_in,
                              void* d_out, int out_size)
{
    const float* s     = (const float*)d_in[0];
    const float* h     = (const float*)d_in[1];
    const float* sh    = (const float*)d_in[2];
    const float* temp  = (const float*)d_in[3];
    const float* temp2 = (const float*)d_in[4];
    const float* Wq_c  = (const float*)d_in[5];
    const float* Wq_s  = (const float*)d_in[6];
    const float* Wk_c  = (const float*)d_in[7];
    const float* Wv_c  = (const float*)d_in[8];
    const float* Wk_s  = (const float*)d_in[9];
    const float* Wv_s  = (const float*)d_in[10];
    float* out = (float*)d_out;

    cudaFuncSetAttribute(proj_mma_kernel, cudaFuncAttributeMaxDynamicSharedMemorySize, PJ_SMEM);
    cudaFuncSetAttribute(xca_mma_kernel,  cudaFuncAttributeMaxDynamicSharedMemorySize, XCA_SMEM);
    cudaFuncSetAttribute(spat_mma_kernel, cudaFuncAttributeMaxDynamicSharedMemorySize, SPAT_SMEM);

    proj_mma_kernel<<<dim3(64, 2, 5), 256, PJ_SMEM>>>(s, sh, Wq_c, Wk_c, Wv_c, Wq_s, Wk_s);
    vproj_kernel<<<128, 256>>>(h, Wv_s);
    chanS_mma_kernel<<<256, 256>>>();
    xca_mma_kernel<<<dim3(16, 16), 256, XCA_SMEM>>>(out, temp);
    spat_mma_kernel<<<256, 256, SPAT_SMEM>>>(out, temp2);
}

// round 15
// speedup vs baseline: 1.0483x; 1.0058x over previous
#include <cuda_runtime.h>
#include <cuda_bf16.h>
#include <cstdint>
#include <math.h>

// ---------------------------------------------------------------------------
// Scratch
// ---------------------------------------------------------------------------
__device__ float g_Qc [4*2048*256];
__device__ float g_Kc [4*2048*256];
__device__ float g_Vc [4*2048*256];
__device__ float g_Qsn[4*2048*256];
__device__ float g_Ksn[4*2048*256];
__device__ float g_Vsn[4*2048*64];
__device__ float g_Scp[16*16*64*64];  // channel gram partials [kc][bh][64*64]
__device__ float g_Ahi[16*64*64];     // softmaxed attention, tf32 hi
__device__ float g_Alo[16*64*64];     // residual lo

// ---------------------------------------------------------------------------
// warp MMA helpers
// ---------------------------------------------------------------------------
__device__ __forceinline__ void mma8(float* c, const uint32_t* a, const uint32_t* b) {
    asm volatile("mma.sync.aligned.m16n8k8.row.col.f32.tf32.tf32.f32 "
        "{%0,%1,%2,%3}, {%4,%5,%6,%7}, {%8,%9}, {%0,%1,%2,%3};"
        : "+f"(c[0]), "+f"(c[1]), "+f"(c[2]), "+f"(c[3])
        : "r"(a[0]), "r"(a[1]), "r"(a[2]), "r"(a[3]), "r"(b[0]), "r"(b[1]));
}
__device__ __forceinline__ void mma16(float* c, const uint32_t* a, const uint32_t* b) {
    asm volatile("mma.sync.aligned.m16n8k16.row.col.f32.bf16.bf16.f32 "
        "{%0,%1,%2,%3}, {%4,%5,%6,%7}, {%8,%9}, {%0,%1,%2,%3};"
        : "+f"(c[0]), "+f"(c[1]), "+f"(c[2]), "+f"(c[3])
        : "r"(a[0]), "r"(a[1]), "r"(a[2]), "r"(a[3]), "r"(b[0]), "r"(b[1]));
}
__device__ __forceinline__ float tf32r(float x) {
    uint32_t u; asm("cvt.rna.tf32.f32 %0, %1;" : "=r"(u) : "f"(x));
    return __uint_as_float(u);
}
__device__ __forceinline__ uint32_t packbf(float e0, float e1) {
    uint32_t r; asm("cvt.rn.bf16x2.f32 %0, %1, %2;" : "=r"(r) : "f"(e1), "f"(e0));
    return r;
}

// ===========================================================================
// Projections: R10 configuration (all tf32; 3-term split only for Wv_c).
// ===========================================================================
#define PSTR 36
#define PJ_AH 0
#define PJ_AL (128*PSTR)
#define PJ_BH (2*128*PSTR)
#define PJ_BL (3*128*PSTR)
#define PJ_SMEM (4*128*PSTR*4)

__global__ void __launch_bounds__(256) proj_mma_kernel(
    const float* __restrict__ s, const float* __restrict__ sh,
    const float* __restrict__ Wq_c, const float* __restrict__ Wk_c,
    const float* __restrict__ Wv_c, const float* __restrict__ Wq_s,
    const float* __restrict__ Wk_s)
{
    extern __shared__ __align__(16) float sm[];
    const int tid = threadIdx.x, wid = tid >> 5, lane = tid & 31;
    const int gid = lane >> 2, tid4 = lane & 3;
    const int wm = wid >> 2, wn = wid & 3;
    const int m0 = blockIdx.x * 128, n0 = blockIdx.y * 128;
    const int sel = blockIdx.z;
    const bool split = (sel == 2);

    const float* X = (sel == 0) ? s : sh;
    const float* W = (sel == 0) ? Wq_c : (sel == 1) ? Wk_c : (sel == 2) ? Wv_c
                   : (sel == 3) ? Wq_s : Wk_s;
    float* dst = (sel == 0) ? g_Qc : (sel == 1) ? g_Kc : (sel == 2) ? g_Vc
               : (sel == 3) ? g_Qsn : g_Ksn;

    float acc[4][4][4];
#pragma unroll
    for (int a = 0; a < 4; a++)
#pragma unroll
        for (int b = 0; b < 4; b++)
#pragma unroll
            for (int c = 0; c < 4; c++) acc[a][b][c] = 0.f;

    for (int kc = 0; kc < 8; kc++) {
        const int k0 = kc * 32;
#pragma unroll
        for (int i = 0; i < 4; i++) {
            int f = tid + i * 256;
            int row = f >> 3, c4 = f & 7;
            float4 v = *(const float4*)&X[(size_t)(m0 + row) * 256 + k0 + c4 * 4];
            float4 hi;
            hi.x = tf32r(v.x); hi.y = tf32r(v.y); hi.z = tf32r(v.z); hi.w = tf32r(v.w);
            *(float4*)&sm[PJ_AH + row * PSTR + c4 * 4] = hi;
            if (split) {
                float4 lo;
                lo.x = v.x - hi.x; lo.y = v.y - hi.y; lo.z = v.z - hi.z; lo.w = v.w - hi.w;
                *(float4*)&sm[PJ_AL + row * PSTR + c4 * 4] = lo;
            }
            float4 w = *(const float4*)&W[(size_t)(n0 + row) * 256 + k0 + c4 * 4];
            hi.x = tf32r(w.x); hi.y = tf32r(w.y); hi.z = tf32r(w.z); hi.w = tf32r(w.w);
            *(float4*)&sm[PJ_BH + row * PSTR + c4 * 4] = hi;
            if (split) {
                float4 lo;
                lo.x = w.x - hi.x; lo.y = w.y - hi.y; lo.z = w.z - hi.z; lo.w = w.w - hi.w;
                *(float4*)&sm[PJ_BL + row * PSTR + c4 * 4] = lo;
            }
        }
        __syncthreads();
#pragma unroll
        for (int kk = 0; kk < 4; kk++) {
            uint32_t ah[4][4], bh[4][2];
#pragma unroll
            for (int mt = 0; mt < 4; mt++) {
                int r = wm * 64 + mt * 16;
                int i0 = (r + gid) * PSTR + kk * 8 + tid4;
                int i1 = (r + gid + 8) * PSTR + kk * 8 + tid4;
                ah[mt][0] = *(uint32_t*)&sm[PJ_AH + i0];
                ah[mt][1] = *(uint32_t*)&sm[PJ_AH + i1];
                ah[mt][2] = *(uint32_t*)&sm[PJ_AH + i0 + 4];
                ah[mt][3] = *(uint32_t*)&sm[PJ_AH + i1 + 4];
            }
#pragma unroll
            for (int nt = 0; nt < 4; nt++) {
                int n = wn * 32 + nt * 8;
                int i0 = (n + gid) * PSTR + kk * 8 + tid4;
                bh[nt][0] = *(uint32_t*)&sm[PJ_BH + i0];
                bh[nt][1] = *(uint32_t*)&sm[PJ_BH + i0 + 4];
            }
#pragma unroll
            for (int mt = 0; mt < 4; mt++)
#pragma unroll
                for (int nt = 0; nt < 4; nt++)
                    mma8(acc[mt][nt], ah[mt], bh[nt]);
            if (split) {
                uint32_t al[4][4], bl[4][2];
#pragma unroll
                for (int mt = 0; mt < 4; mt++) {
                    int r = wm * 64 + mt * 16;
                    int i0 = (r + gid) * PSTR + kk * 8 + tid4;
                    int i1 = (r + gid + 8) * PSTR + kk * 8 + tid4;
                    al[mt][0] = *(uint32_t*)&sm[PJ_AL + i0];
                    al[mt][1] = *(uint32_t*)&sm[PJ_AL + i1];
                    al[mt][2] = *(uint32_t*)&sm[PJ_AL + i0 + 4];
                    al[mt][3] = *(uint32_t*)&sm[PJ_AL + i1 + 4];
                }
#pragma unroll
                for (int nt = 0; nt < 4; nt++) {
                    int n = wn * 32 + nt * 8;
                    int i0 = (n + gid) * PSTR + kk * 8 + tid4;
                    bl[nt][0] = *(uint32_t*)&sm[PJ_BL + i0];
                    bl[nt][1] = *(uint32_t*)&sm[PJ_BL + i0 + 4];
                }
#pragma unroll
                for (int mt = 0; mt < 4; mt++)
#pragma unroll
                    for (int nt = 0; nt < 4; nt++) {
                        mma8(acc[mt][nt], ah[mt], bl[nt]);
                        mma8(acc[mt][nt], al[mt], bh[nt]);
                    }
            }
        }
        __syncthreads();
    }
#pragma unroll
    for (int mt = 0; mt < 4; mt++)
#pragma unroll
        for (int nt = 0; nt < 4; nt++) {
            int m = m0 + wm * 64 + mt * 16 + gid;
            int n = n0 + wn * 32 + nt * 8 + tid4 * 2;
            dst[(size_t)m * 256 + n]           = acc[mt][nt][0];
            dst[(size_t)m * 256 + n + 1]       = acc[mt][nt][1];
            dst[(size_t)(m + 8) * 256 + n]     = acc[mt][nt][2];
            dst[(size_t)(m + 8) * 256 + n + 1] = acc[mt][nt][3];
        }
}

// ===========================================================================
// v_s projection (scalar fp32, K=64)
// ===========================================================================
__global__ __launch_bounds__(256) void vproj_kernel(const float* __restrict__ X,
                                                    const float* __restrict__ W)
{
    __shared__ __align__(16) float Xs[16][68], Ws[16][68];
    const int tid = threadIdx.x, tx = tid & 15, ty = tid >> 4, m0 = blockIdx.x * 64;
    const int lkk = tid & 15, lrow = tid >> 4;
    float acc[4][4];
#pragma unroll
    for (int u = 0; u < 4; u++)
#pragma unroll
        for (int v = 0; v < 4; v++) acc[u][v] = 0.f;
    for (int k0 = 0; k0 < 64; k0 += 16) {
#pragma unroll
        for (int i = 0; i < 4; i++) {
            int row = lrow + i * 16;
            Xs[lkk][row] = X[(m0 + row) * 64 + k0 + lkk];
            Ws[lkk][row] = W[row * 64 + k0 + lkk];
        }
        __syncthreads();
#pragma unroll
        for (int k = 0; k < 16; k++) {
            float4 a = *(const float4*)&Xs[k][ty * 4];
            float4 w = *(const float4*)&Ws[k][tx * 4];
            acc[0][0]+=a.x*w.x; acc[0][1]+=a.x*w.y; acc[0][2]+=a.x*w.z; acc[0][3]+=a.x*w.w;
            acc[1][0]+=a.y*w.x; acc[1][1]+=a.y*w.y; acc[1][2]+=a.y*w.z; acc[1][3]+=a.y*w.w;
            acc[2][0]+=a.z*w.x; acc[2][1]+=a.z*w.y; acc[2][2]+=a.z*w.z; acc[2][3]+=a.z*w.w;
            acc[3][0]+=a.w*w.x; acc[3][1]+=a.w*w.y; acc[3][2]+=a.w*w.z; acc[3][3]+=a.w*w.w;
        }
        __syncthreads();
    }
#pragma unroll
    for (int u = 0; u < 4; u++)
#pragma unroll
        for (int v = 0; v < 4; v++)
            g_Vsn[(size_t)(m0 + ty * 4 + u) * 64 + tx * 4 + v] = acc[u][v];
}

// ===========================================================================
// Channel gram partials (GSTR 37, grid 256) — unchanged from R14 win
// ===========================================================================
#define GSTR 37
__global__ void __launch_bounds__(256) chanS_mma_kernel()
{
    __shared__ __align__(16) float Qt[64 * GSTR], Kt[64 * GSTR];
    const int tid = threadIdx.x, wid = tid >> 5, lane = tid & 31;
    const int gid = lane >> 2, tid4 = lane & 3;
    const int wm = wid >> 2, wn = wid & 3;
    const int cid = blockIdx.x, bh = cid >> 4, kc = cid & 15;
    const int b = bh >> 2, h = bh & 3;

    float acc[2][2][4];
#pragma unroll
    for (int a = 0; a < 2; a++)
#pragma unroll
        for (int c = 0; c < 2; c++)
#pragma unroll
            for (int d = 0; d < 4; d++) acc[a][c][d] = 0.f;

    const int lr = tid >> 3;
    const int ch0 = (tid & 7) * 8;

    for (int kt = 0; kt < 4; kt++) {
        int cm = kc * 128 + kt * 32 + lr;
        int r = cm >> 2, t = cm & 3;
        const float* qb = &g_Qc[(size_t)(b * 2048 + h * 512 + r) * 256 + t * 64 + ch0];
        const float* kb = &g_Kc[(size_t)(b * 2048 + h * 512 + r) * 256 + t * 64 + ch0];
        float4 q0 = *(const float4*)qb, q1 = *(const float4*)(qb + 4);
        float4 k0 = *(const float4*)kb, k1 = *(const float4*)(kb + 4);
        Qt[(ch0+0)*GSTR + lr] = tf32r(q0.x); Qt[(ch0+1)*GSTR + lr] = tf32r(q0.y);
        Qt[(ch0+2)*GSTR + lr] = tf32r(q0.z); Qt[(ch0+3)*GSTR + lr] = tf32r(q0.w);
        Qt[(ch0+4)*GSTR + lr] = tf32r(q1.x); Qt[(ch0+5)*GSTR + lr] = tf32r(q1.y);
        Qt[(ch0+6)*GSTR + lr] = tf32r(q1.z); Qt[(ch0+7)*GSTR + lr] = tf32r(q1.w);
        Kt[(ch0+0)*GSTR + lr] = tf32r(k0.x); Kt[(ch0+1)*GSTR + lr] = tf32r(k0.y);
        Kt[(ch0+2)*GSTR + lr] = tf32r(k0.z); Kt[(ch0+3)*GSTR + lr] = tf32r(k0.w);
        Kt[(ch0+4)*GSTR + lr] = tf32r(k1.x); Kt[(ch0+5)*GSTR + lr] = tf32r(k1.y);
        Kt[(ch0+6)*GSTR + lr] = tf32r(k1.z); Kt[(ch0+7)*GSTR + lr] = tf32r(k1.w);
        __syncthreads();
#pragma unroll
        for (int kk = 0; kk < 4; kk++) {
            uint32_t af[2][4], bf[2][2];
#pragma unroll
            for (int mt = 0; mt < 2; mt++) {
                int rI = wm * 32 + mt * 16;
                int i0 = (rI + gid) * GSTR + kk * 8 + tid4;
                int i1 = (rI + gid + 8) * GSTR + kk * 8 + tid4;
                af[mt][0] = *(uint32_t*)&Qt[i0];
                af[mt][1] = *(uint32_t*)&Qt[i1];
                af[mt][2] = *(uint32_t*)&Qt[i0 + 4];
                af[mt][3] = *(uint32_t*)&Qt[i1 + 4];
            }
#pragma unroll
            for (int nt = 0; nt < 2; nt++) {
                int n = wn * 16 + nt * 8;
                int i0 = (n + gid) * GSTR + kk * 8 + tid4;
                bf[nt][0] = *(uint32_t*)&Kt[i0];
                bf[nt][1] = *(uint32_t*)&Kt[i0 + 4];
            }
#pragma unroll
            for (int mt = 0; mt < 2; mt++)
#pragma unroll
                for (int nt = 0; nt < 2; nt++)
                    mma8(acc[mt][nt], af[mt], bf[nt]);
        }
        __syncthreads();
    }
#pragma unroll
    for (int mt = 0; mt < 2; mt++)
#pragma unroll
        for (int nt = 0; nt < 2; nt++) {
            int i = wm * 32 + mt * 16 + gid;
            int j = wn * 16 + nt * 8 + tid4 * 2;
            float* o = &g_Scp[((kc * 16 + bh) << 12)];
            o[i*64 + j]       = acc[mt][nt][0];
            o[i*64 + j + 1]   = acc[mt][nt][1];
            o[(i+8)*64 + j]   = acc[mt][nt][2];
            o[(i+8)*64 + j+1] = acc[mt][nt][3];
        }
}

// ===========================================================================
// chan_soft: reduce 16 partials + softmax + tf32 hi/lo split, ONCE per bh.
// grid (16 bh, 8 row-groups), 256 threads = 8 warps, warp = one row.
// ===========================================================================
__global__ void __launch_bounds__(256) chan_soft_kernel(const float* __restrict__ temp)
{
    const int bh = blockIdx.x, rg = blockIdx.y;
    const int wid = threadIdx.x >> 5, lane = threadIdx.x & 31;
    const int h = bh & 3;
    const int row = rg * 8 + wid;
    const float scale = 0.125f * temp[h];
    const int base = row * 64 + lane * 2;

    float s0 = 0.f, s1 = 0.f;
#pragma unroll
    for (int p = 0; p < 16; p++) {
        const float* src = &g_Scp[((p * 16 + bh) << 12) + base];
        s0 += src[0];
        s1 += src[1];
    }
    float e0 = __expf(s0 * scale), e1 = __expf(s1 * scale);
    float ws = e0 + e1;
#pragma unroll
    for (int off = 16; off > 0; off >>= 1)
        ws += __shfl_xor_sync(0xFFFFFFFF, ws, off);
    float inv = 1.f / ws;
    float a0 = e0 * inv, a1 = e1 * inv;
    float h0 = tf32r(a0), h1 = tf32r(a1);
    float* dh = &g_Ahi[(bh << 12) + base];
    float* dl = &g_Alo[(bh << 12) + base];
    dh[0] = h0; dh[1] = h1;
    dl[0] = a0 - h0; dl[1] = a1 - h1;
}

// ===========================================================================
// x_ca: pure GEMM now — A pre-split in g_Ahi/g_Alo.  grid (16, 16).
// ===========================================================================
#define XSTR 68
#define XA_HI 0
#define XA_LO (64*XSTR)
#define XB_HI (2*64*XSTR)
#define XB_LO (XB_HI + 128*XSTR)
#define XCA_SMEM ((XB_LO + 128*XSTR) * 4)

__global__ void __launch_bounds__(256) xca_mma_kernel(float* __restrict__ out)
{
    extern __shared__ __align__(16) float sm[];
    const int tid = threadIdx.x, wid = tid >> 5, lane = tid & 31;
    const int gid = lane >> 2, tid4 = lane & 3;
    const int wm = wid >> 2, wn = wid & 3;
    const int bh = blockIdx.x, chunk = blockIdx.y, b = bh >> 2, h = bh & 3;

    // load pre-split A (coalesced)
#pragma unroll
    for (int i = 0; i < 4; i++) {
        int f4 = tid + i * 256;
        int row = f4 >> 4, c = (f4 & 15) * 4;
        *(float4*)&sm[XA_HI + row * XSTR + c] = *(const float4*)&g_Ahi[(bh << 12) + row * 64 + c];
        *(float4*)&sm[XA_LO + row * XSTR + c] = *(const float4*)&g_Alo[(bh << 12) + row * 64 + c];
    }
    // load + split V chunk
#pragma unroll
    for (int i = 0; i < 8; i++) {
        int f4 = tid + i * 256;
        int lrw = f4 >> 4, c = (f4 & 15) * 4;
        int np = chunk * 128 + lrw;
        int r = np >> 2, t = np & 3;
        float4 v = *(const float4*)&g_Vc[(size_t)(b * 2048 + h * 512 + r) * 256 + t * 64 + c];
        float4 hi, lo;
        hi.x = tf32r(v.x); lo.x = v.x - hi.x; hi.y = tf32r(v.y); lo.y = v.y - hi.y;
        hi.z = tf32r(v.z); lo.z = v.z - hi.z; hi.w = tf32r(v.w); lo.w = v.w - hi.w;
        *(float4*)&sm[XB_HI + lrw * XSTR + c] = hi;
        *(float4*)&sm[XB_LO + lrw * XSTR + c] = lo;
    }
    __syncthreads();

    float acc[2][4][4];
#pragma unroll
    for (int a = 0; a < 2; a++)
#pragma unroll
        for (int c = 0; c < 4; c++)
#pragma unroll
            for (int d = 0; d < 4; d++) acc[a][c][d] = 0.f;

#pragma unroll
    for (int kk = 0; kk < 8; kk++) {
        uint32_t ah[2][4], al[2][4], bh4[4][2], bl4[4][2];
#pragma unroll
        for (int mt = 0; mt < 2; mt++) {
            int rI = wm * 32 + mt * 16;
            int i0 = (rI + gid) * XSTR + kk * 8 + tid4;
            int i1 = (rI + gid + 8) * XSTR + kk * 8 + tid4;
            ah[mt][0] = *(uint32_t*)&sm[XA_HI + i0];
            ah[mt][1] = *(uint32_t*)&sm[XA_HI + i1];
            ah[mt][2] = *(uint32_t*)&sm[XA_HI + i0 + 4];
            ah[mt][3] = *(uint32_t*)&sm[XA_HI + i1 + 4];
            al[mt][0] = *(uint32_t*)&sm[XA_LO + i0];
            al[mt][1] = *(uint32_t*)&sm[XA_LO + i1];
            al[mt][2] = *(uint32_t*)&sm[XA_LO + i0 + 4];
            al[mt][3] = *(uint32_t*)&sm[XA_LO + i1 + 4];
        }
#pragma unroll
        for (int nt = 0; nt < 4; nt++) {
            int n = wn * 32 + nt * 8;
            int i0 = (n + gid) * XSTR + kk * 8 + tid4;
            bh4[nt][0] = *(uint32_t*)&sm[XB_HI + i0];
            bh4[nt][1] = *(uint32_t*)&sm[XB_HI + i0 + 4];
            bl4[nt][0] = *(uint32_t*)&sm[XB_LO + i0];
            bl4[nt][1] = *(uint32_t*)&sm[XB_LO + i0 + 4];
        }
#pragma unroll
        for (int mt = 0; mt < 2; mt++)
#pragma unroll
            for (int nt = 0; nt < 4; nt++) {
                mma8(acc[mt][nt], ah[mt], bh4[nt]);
                mma8(acc[mt][nt], ah[mt], bl4[nt]);
                mma8(acc[mt][nt], al[mt], bh4[nt]);
            }
    }

#pragma unroll
    for (int mt = 0; mt < 2; mt++)
#pragma unroll
        for (int nt = 0; nt < 4; nt++) {
            int dc = wm * 32 + mt * 16 + gid;
            int np = chunk * 128 + wn * 32 + nt * 8 + tid4 * 2;
            int f0 = h * 131072 + dc * 2048 + np;
            *(float2*)&out[(size_t)(b * 2048 + (f0 >> 8)) * 320 + (f0 & 255)] =
                make_float2(acc[mt][nt][0], acc[mt][nt][1]);
            int f1 = f0 + 8 * 2048;
            *(float2*)&out[(size_t)(b * 2048 + (f1 >> 8)) * 320 + (f1 & 255)] =
                make_float2(acc[mt][nt][2], acc[mt][nt][3]);
        }
}

// ===========================================================================
// Spatial flash attention (unchanged from R10 win)
// ===========================================================================
#define SP_Q    0
#define SP_K    18432
#define SP_V    36864
#define SP_RS   41216
#define SP_VP   49408
#define SP_RSUM 53504
#define SP_CSUM 54016
#define SP_OS   0
#define SPAT_SMEM 54080

__global__ void __launch_bounds__(256, 2) spat_mma_kernel(float* __restrict__ out,
                                                          const float* __restrict__ temp2)
{
    extern __shared__ __align__(16) char smc[];
    __nv_bfloat16* sQ = (__nv_bfloat16*)(smc + SP_Q);
    __nv_bfloat16* sK = (__nv_bfloat16*)(smc + SP_K);
    __nv_bfloat16* sV = (__nv_bfloat16*)(smc + SP_V);
    float* RSa   = (float*)(smc + SP_RS);
    float* VPa   = (float*)(smc + SP_VP);
    float* RSUMa = (float*)(smc + SP_RSUM);
    float* CSUMa = (float*)(smc + SP_CSUM);

    const int tid = threadIdx.x, wid = tid >> 5, lane = tid & 31;
    const int gid = lane >> 2, t4 = lane & 3;
    const int wq = wid >> 2, wj = wid & 3;
    const int cid = blockIdx.x, qt = cid & 15, bh = cid >> 4, b = bh >> 2, h = bh & 3;
    const float scale = 0.125f * temp2[h];

    const float4* Qg = (const float4*)(g_Qsn + (size_t)(b * 2048 + h * 512 + qt * 32) * 256);
#pragma unroll
    for (int i = 0; i < 8; i++) {
        int f = tid + i * 256;
        float4 v = Qg[f];
        int q = (f >> 6) * 4 + ((f >> 4) & 3);
        int d = (f & 15) * 4;
        uint32_t* dp = (uint32_t*)&sQ[q * 72 + d];
        dp[0] = packbf(v.x * scale, v.y * scale);
        dp[1] = packbf(v.z * scale, v.w * scale);
    }

    float oc[4][2][4];
#pragma unroll
    for (int a = 0; a < 4; a++)
#pragma unroll
        for (int c = 0; c < 2; c++)
#pragma unroll
            for (int d = 0; d < 4; d++) oc[a][c][d] = 0.f;
    float lpart[8];
#pragma unroll
    for (int j = 0; j < 8; j++) lpart[j] = 0.f;
    float4 vpart = make_float4(0.f, 0.f, 0.f, 0.f);

    for (int t = 0; t < 16; t++) {
        const float4* Kg = (const float4*)(g_Ksn + (size_t)(b * 2048 + h * 512 + t * 32) * 256);
#pragma unroll
        for (int i = 0; i < 8; i++) {
            int f = tid + i * 256;
            float4 v = Kg[f];
            int q = (f >> 6) * 4 + ((f >> 4) & 3);
            int d = (f & 15) * 4;
            uint32_t* dp = (uint32_t*)&sK[q * 72 + d];
            dp[0] = packbf(v.x, v.y);
            dp[1] = packbf(v.z, v.w);
        }
        const float4* Vg = (const float4*)(g_Vsn + (size_t)(b * 2048 + h * 512 + t * 32) * 64);
#pragma unroll
        for (int u = 0; u < 2; u++) {
            int f = tid + u * 256;
            float4 v = Vg[f];
            vpart.x += v.x; vpart.y += v.y; vpart.z += v.z; vpart.w += v.w;
            int j = (f >> 4) * 4 + ((f & 15) >> 2);
            int dv = (f & 3) * 4;
            sV[(dv + 0) * 136 + j] = __float2bfloat16_rn(v.x);
            sV[(dv + 1) * 136 + j] = __float2bfloat16_rn(v.y);
            sV[(dv + 2) * 136 + j] = __float2bfloat16_rn(v.z);
            sV[(dv + 3) * 136 + j] = __float2bfloat16_rn(v.w);
        }
        __syncthreads();

#pragma unroll
        for (int mp = 0; mp < 2; mp++) {
            float accS[2][4][4];
#pragma unroll
            for (int a = 0; a < 2; a++)
#pragma unroll
                for (int c = 0; c < 4; c++)
#pragma unroll
                    for (int d = 0; d < 4; d++) accS[a][c][d] = 0.f;

#pragma unroll
            for (int kk = 0; kk < 4; kk++) {
                uint32_t bK[4][2];
#pragma unroll
                for (int nt = 0; nt < 4; nt++) {
                    int n = wj * 32 + nt * 8 + gid;
                    const uint32_t* p = (const uint32_t*)&sK[n * 72 + kk * 16 + 2 * t4];
                    bK[nt][0] = p[0];
                    bK[nt][1] = p[4];
                }
#pragma unroll
                for (int mi = 0; mi < 2; mi++) {
                    int r = wq * 64 + (mp * 2 + mi) * 16;
                    const uint32_t* pa = (const uint32_t*)&sQ[(r + gid) * 72 + kk * 16 + 2 * t4];
                    const uint32_t* pb = (const uint32_t*)&sQ[(r + gid + 8) * 72 + kk * 16 + 2 * t4];
                    uint32_t a[4] = { pa[0], pb[0], pa[4], pb[4] };
#pragma unroll
                    for (int nt = 0; nt < 4; nt++)
                        mma16(accS[mi][nt], a, bK[nt]);
                }
            }

            uint32_t pA[2][2][4];
#pragma unroll
            for (int mi = 0; mi < 2; mi++) {
#pragma unroll
                for (int nt = 0; nt < 4; nt++) {
                    float pm[4];
#pragma unroll
                    for (int c = 0; c < 4; c++) {
                        float x = accS[mi][nt][c];
                        float tt = fmaf(x, 0.16666667f, 0.5f);
                        tt = fmaf(x, tt, 1.0f);
                        pm[c] = x * tt;
                    }
                    lpart[(mp * 2 + mi) * 2]     += pm[0] + pm[1];
                    lpart[(mp * 2 + mi) * 2 + 1] += pm[2] + pm[3];
                    int kk2 = nt >> 1, half = nt & 1;
                    pA[mi][kk2][half ? 2 : 0] = packbf(pm[0], pm[1]);
                    pA[mi][kk2][half ? 3 : 1] = packbf(pm[2], pm[3]);
                }
            }
#pragma unroll
            for (int kk2 = 0; kk2 < 2; kk2++) {
                uint32_t bV[2][2];
#pragma unroll
                for (int ntv = 0; ntv < 2; ntv++) {
                    const uint32_t* p = (const uint32_t*)&sV[(ntv * 8 + gid) * 136 + wj * 32 + kk2 * 16 + 2 * t4];
                    bV[ntv][0] = p[0];
                    bV[ntv][1] = p[4];
                }
#pragma unroll
                for (int mi = 0; mi < 2; mi++)
#pragma unroll
                    for (int ntv = 0; ntv < 2; ntv++)
                        mma16(oc[mp * 2 + mi][ntv], pA[mi][kk2], bV[ntv]);
            }
        }
        __syncthreads();
    }

#pragma unroll
    for (int j = 0; j < 8; j++) {
        int row = wq * 64 + (j >> 1) * 16 + (j & 1) * 8 + gid;
        RSa[row * 16 + wj * 4 + t4] = lpart[j];
    }
    *(float4*)&VPa[tid * 4] = vpart;
    float* OS = (float*)(smc + SP_OS);
#pragma unroll
    for (int mt = 0; mt < 4; mt++)
#pragma unroll
        for (int ntv = 0; ntv < 2; ntv++) {
            int r = wq * 64 + mt * 16 + gid;
            *(float2*)&OS[wj * 2048 + r * 16 + ntv * 8 + 2 * t4] =
                make_float2(oc[mt][ntv][0], oc[mt][ntv][1]);
            *(float2*)&OS[wj * 2048 + (r + 8) * 16 + ntv * 8 + 2 * t4] =
                make_float2(oc[mt][ntv][2], oc[mt][ntv][3]);
        }
    __syncthreads();
    if (tid < 128) {
        float a = 0.f;
#pragma unroll
        for (int i = 0; i < 16; i++) a += RSa[tid * 16 + i];
        RSUMa[tid] = 2048.0f + a;
    }
    if (tid < 16) {
        int g = tid >> 2, comp = tid & 3;
        float a = 0.f;
        for (int j = 0; j < 64; j++) a += VPa[(j * 4 + g) * 4 + comp];
        CSUMa[tid] = a;
    }
    __syncthreads();

    const int row = tid >> 1, c0 = (tid & 1) * 8;
    const float inv = 1.f / RSUMa[row];
    float x[8];
#pragma unroll
    for (int i = 0; i < 8; i++) {
        float o = CSUMa[c0 + i];
#pragma unroll
        for (int w = 0; w < 4; w++) o += OS[w * 2048 + row * 16 + c0 + i];
        x[i] = o * inv;
    }
    const int n = qt * 128 + row;
    const int f0 = h * 32768 + n * 16 + c0;
    float* og = out + (size_t)(b * 2048 + (f0 >> 6)) * 320 + 256 + (f0 & 63);
    *(float4*)&og[0] = make_float4(x[0], x[1], x[2], x[3]);
    *(float4*)&og[4] = make_float4(x[4], x[5], x[6], x[7]);
}

// ===========================================================================
// Launcher
// ===========================================================================
extern "C" void kernel_launch(void* const* d_in, const int* in_sizes, int n_in,
                              void* d_out, int out_size)
{
    const float* s     = (const float*)d_in[0];
    const float* h     = (const float*)d_in[1];
    const float* sh    = (const float*)d_in[2];
    const float* temp  = (const float*)d_in[3];
    const float* temp2 = (const float*)d_in[4];
    const float* Wq_c  = (const float*)d_in[5];
    const float* Wq_s  = (const float*)d_in[6];
    const float* Wk_c  = (const float*)d_in[7];
    const float* Wv_c  = (const float*)d_in[8];
    const float* Wk_s  = (const float*)d_in[9];
    const float* Wv_s  = (const float*)d_in[10];
    float* out = (float*)d_out;

    cudaFuncSetAttribute(proj_mma_kernel, cudaFuncAttributeMaxDynamicSharedMemorySize, PJ_SMEM);
    cudaFuncSetAttribute(xca_mma_kernel,  cudaFuncAttributeMaxDynamicSharedMemorySize, XCA_SMEM);
    cudaFuncSetAttribute(spat_mma_kernel, cudaFuncAttributeMaxDynamicSharedMemorySize, SPAT_SMEM);

    proj_mma_kernel<<<dim3(64, 2, 5), 256, PJ_SMEM>>>(s, sh, Wq_c, Wk_c, Wv_c, Wq_s, Wk_s);
    vproj_kernel<<<128, 256>>>(h, Wv_s);
    chanS_mma_kernel<<<256, 256>>>();
    chan_soft_kernel<<<dim3(16, 8), 256>>>(temp);
    xca_mma_kernel<<<dim3(16, 16), 256, XCA_SMEM>>>(out);
    spat_mma_kernel<<<256, 256, SPAT_SMEM>>>(out, temp2);
}